// round 10
// baseline (speedup 1.0000x reference)
#include <cuda_runtime.h>
#include <cstdint>

#define NN    50000
#define EE    200000
#define GG    128
#define FIN   40
#define H512  512
#define H1024 1024
#define FC    2048
#define NCLS  345
#define NB_SCAN ((NN + 255) / 256)

// pre-rounded weight scratch offsets (floats), layout [K][N] (original)
#define W2R_OFF  0
#define C6_OFF   262144
#define C7_OFF   786432
#define C8_OFF   1835008
#define FC1_OFF  2883584
#define WR_TOTAL 4980736

// dynamic smem for fastgemm: As[2][128][20] + Bs[2][16][264] floats
#define FG_AS_FLOATS (2 * 128 * 20)
#define FG_BS_FLOATS (2 * 16 * 264)
#define FG_SMEM ((FG_AS_FLOATS + FG_BS_FLOATS) * 4)

// ---------------- scratch (static device globals; no allocations) ----------
__device__ float g_bufA[(size_t)NN * H1024];
__device__ float g_bufB[(size_t)NN * H1024];
__device__ float g_bufC[(size_t)NN * H1024];
__device__ float g_wr[WR_TOTAL];
__device__ float g_ew[EE];
__device__ float g_deg[NN];
__device__ float g_dis[NN];
__device__ float g_pooled[GG * H1024];
__device__ float g_z[GG * FC];
__device__ int   g_is64;

// CSR (by destination)
__device__ int   g_ecnt[NN];
__device__ int   g_rowstart[NN];
__device__ int   g_next[NN];
__device__ int   g_csr_src[EE];
__device__ float g_csr_w[EE];
__device__ int   g_blksum[NB_SCAN];

#define BUF_A      0
#define BUF_B      1
#define BUF_C      2
#define BUF_POOLED 3
#define BUF_Z      4
__device__ __forceinline__ float* sel(int id) {
    switch (id) {
        case BUF_A:      return g_bufA;
        case BUF_B:      return g_bufB;
        case BUF_C:      return g_bufC;
        case BUF_POOLED: return g_pooled;
        case BUF_Z:      return g_z;
    }
    return nullptr;
}

__device__ __forceinline__ int ld_idx(const void* p, long long i) {
    return g_is64 ? (int)((const long long*)p)[i] : ((const int*)p)[i];
}

__device__ __forceinline__ uint32_t f2tf(float x) {
    uint32_t u;
    asm("cvt.rna.tf32.f32 %0, %1;" : "=r"(u) : "f"(x));
    return u;
}
__device__ __forceinline__ float tf32r(float x) {
    uint32_t u;
    asm("cvt.rna.tf32.f32 %0, %1;" : "=r"(u) : "f"(x));
    return __uint_as_float(u);
}

#define CP_ASYNC16(dst_u32, src_ptr) \
    asm volatile("cp.async.ca.shared.global [%0], [%1], 16;\n" :: "r"(dst_u32), "l"(src_ptr))
#define CP_COMMIT() asm volatile("cp.async.commit_group;\n" ::: "memory")
#define CP_WAIT0()  asm volatile("cp.async.wait_group 0;\n" ::: "memory")
#define CP_WAIT1()  asm volatile("cp.async.wait_group 1;\n" ::: "memory")

// ---------------- dtype detection ------------------------------------------
__global__ void k_detect(const unsigned int* __restrict__ ei_words) {
    __shared__ int found;
    if (threadIdx.x == 0) found = 0;
    __syncthreads();
    for (int i = 1 + 2 * threadIdx.x; i < 4096; i += 2 * blockDim.x)
        if (ei_words[i] != 0u) found = 1;
    __syncthreads();
    if (threadIdx.x == 0) g_is64 = (found ? 0 : 1);
}

__global__ void k_init() {
    int i = blockIdx.x * blockDim.x + threadIdx.x;
    if (i < NN) { g_deg[i] = 1.0f; g_ecnt[i] = 0; }
}

// ---------------- weight pre-rounding (tf32 rna, once per launch) ----------
__global__ void k_round5(const float* __restrict__ w2, const float* __restrict__ c6,
                         const float* __restrict__ c7, const float* __restrict__ c8,
                         const float* __restrict__ f1) {
    int i = blockIdx.x * 256 + threadIdx.x;
    if (i >= WR_TOTAL) return;
    float v;
    if      (i < C6_OFF)  v = w2[i - W2R_OFF];
    else if (i < C7_OFF)  v = c6[i - C6_OFF];
    else if (i < C8_OFF)  v = c7[i - C7_OFF];
    else if (i < FC1_OFF) v = c8[i - C8_OFF];
    else                  v = f1[i - FC1_OFF];
    g_wr[i] = tf32r(v);
}

// ---------------- edge MLP --------------------------------------------------
__global__ void k_edge_mlp(const float* __restrict__ ea,
                           const float* __restrict__ w1, const float* __restrict__ b1,
                           const float* __restrict__ w2, const float* __restrict__ b2) {
    int e = blockIdx.x * blockDim.x + threadIdx.x;
    if (e >= EE) return;
    float a0 = ea[e * 3 + 0], a1 = ea[e * 3 + 1], a2 = ea[e * 3 + 2];
    float acc = b2[0];
#pragma unroll 8
    for (int h = 0; h < 64; h++) {
        float v = b1[h] + a0 * w1[h] + a1 * w1[64 + h] + a2 * w1[128 + h];
        acc += fmaxf(v, 0.0f) * w2[h];
    }
    g_ew[e] = 1.0f / (1.0f + expf(-acc));
}

__global__ void k_degcnt(const void* __restrict__ ei) {
    int e = blockIdx.x * blockDim.x + threadIdx.x;
    if (e >= EE) return;
    int d = ld_idx(ei, (long long)EE + e);
    if (d >= 0 && d < NN) {
        atomicAdd(&g_deg[d], g_ew[e]);
        atomicAdd(&g_ecnt[d], 1);
    }
}

__global__ void k_dis() {
    int i = blockIdx.x * blockDim.x + threadIdx.x;
    if (i >= NN) return;
    g_dis[i] = rsqrtf(g_deg[i]);
}

// ---------------- CSR build --------------------------------------------------
__global__ void k_scan_block() {
    __shared__ int s[256];
    int tid = threadIdx.x;
    int i = blockIdx.x * 256 + tid;
    int v = (i < NN) ? g_ecnt[i] : 0;
    s[tid] = v;
    __syncthreads();
#pragma unroll
    for (int off = 1; off < 256; off <<= 1) {
        int t = (tid >= off) ? s[tid - off] : 0;
        __syncthreads();
        s[tid] += t;
        __syncthreads();
    }
    if (i < NN) g_rowstart[i] = s[tid] - v;
    if (tid == 255) g_blksum[blockIdx.x] = s[tid];
}

__global__ void k_scan_tops() {
    if (threadIdx.x == 0 && blockIdx.x == 0) {
        int run = 0;
        for (int b = 0; b < NB_SCAN; b++) {
            int t = g_blksum[b];
            g_blksum[b] = run;
            run += t;
        }
    }
}

__global__ void k_scan_add() {
    int i = blockIdx.x * 256 + threadIdx.x;
    if (i >= NN) return;
    int r = g_rowstart[i] + g_blksum[blockIdx.x];
    g_rowstart[i] = r;
    g_next[i] = r;
}

__global__ void k_fill(const void* __restrict__ ei) {
    int e = blockIdx.x * blockDim.x + threadIdx.x;
    if (e >= EE) return;
    int s = ld_idx(ei, e);
    int d = ld_idx(ei, (long long)EE + e);
    if (s < 0 || s >= NN || d < 0 || d >= NN) return;
    int pos = atomicAdd(&g_next[d], 1);
    g_csr_src[pos] = s;
    g_csr_w[pos]   = g_dis[s] * g_ew[e] * g_dis[d];
}

// ---------------- FAST tf32 GEMM: cp.async, CTA 128x256, 16 warps 32x64 -----
// Requirements: K%16==0, N%256==0, inputs pre-rounded. B = g_wr + bOff, [K][N].
__global__ __launch_bounds__(512) void k_fastgemm(
    int aId, int bOff, const float* __restrict__ bias, int cId,
    int M, int N, int K, int doRelu, int doRound)
{
    extern __shared__ float smemF[];
    float (*As)[128][20] = (float(*)[128][20])smemF;                    // [buf][m][k]
    float (*Bs)[16][264] = (float(*)[16][264])(smemF + FG_AS_FLOATS);   // [buf][k][n]

    const float* __restrict__ A = sel(aId);
    const float* __restrict__ B = g_wr + bOff;
    float* __restrict__ C       = sel(cId);

    const int tid  = threadIdx.x;
    const int wid  = tid >> 5;
    const int lane = tid & 31;
    const int grp  = lane >> 2;
    const int tg   = lane & 3;
    const int warp_m = wid & 3;    // 4 warps along M (32 rows each)
    const int warp_n = wid >> 2;   // 4 warps along N (64 cols each)

    const int blockRow = blockIdx.y * 128;
    const int blockCol = blockIdx.x * 256;

    float acc[2][8][4];
#pragma unroll
    for (int mi = 0; mi < 2; mi++)
#pragma unroll
        for (int ni = 0; ni < 8; ni++)
#pragma unroll
            for (int r = 0; r < 4; r++) acc[mi][ni][r] = 0.0f;

    const int kIters = K >> 4;

    // A: 128x16 = 512 float4 chunks (1/thread); B: 16x256 = 1024 chunks (2/thread)
    int ar0 = tid >> 2, ak0 = (tid & 3) << 2;
    int agr0 = min(blockRow + ar0, M - 1);

    uint32_t asB[2], bsB[2];
    asB[0] = (uint32_t)__cvta_generic_to_shared(&As[0][0][0]);
    asB[1] = (uint32_t)__cvta_generic_to_shared(&As[1][0][0]);
    bsB[0] = (uint32_t)__cvta_generic_to_shared(&Bs[0][0][0]);
    bsB[1] = (uint32_t)__cvta_generic_to_shared(&Bs[1][0][0]);

    auto load_tile = [&](int it, int buf) {
        const int k0 = it << 4;
        CP_ASYNC16(asB[buf] + (ar0 * 20 + ak0) * 4, A + (size_t)agr0 * K + k0 + ak0);
#pragma unroll
        for (int i = 0; i < 2; i++) {
            int q = tid + i * 512;
            int br = q >> 6;               // 0..15
            int bn = (q & 63) << 2;        // 0..252
            CP_ASYNC16(bsB[buf] + (br * 264 + bn) * 4, B + (size_t)(k0 + br) * N + blockCol + bn);
        }
        CP_COMMIT();
    };

    load_tile(0, 0);

    for (int it = 0; it < kIters; it++) {
        const int buf = it & 1;
        if (it + 1 < kIters) {
            load_tile(it + 1, buf ^ 1);
            CP_WAIT1();
        } else {
            CP_WAIT0();
        }
        __syncthreads();

#pragma unroll
        for (int ks = 0; ks < 2; ks++) {
            const int kb = ks * 8;
            uint32_t af[2][4], bf[8][2];
#pragma unroll
            for (int mi = 0; mi < 2; mi++) {
                int rb = warp_m * 32 + mi * 16;
                af[mi][0] = __float_as_uint(As[buf][rb + grp][kb + tg]);
                af[mi][1] = __float_as_uint(As[buf][rb + grp + 8][kb + tg]);
                af[mi][2] = __float_as_uint(As[buf][rb + grp][kb + tg + 4]);
                af[mi][3] = __float_as_uint(As[buf][rb + grp + 8][kb + tg + 4]);
            }
#pragma unroll
            for (int ni = 0; ni < 8; ni++) {
                int nb = warp_n * 64 + ni * 8;
                bf[ni][0] = __float_as_uint(Bs[buf][kb + tg][nb + grp]);
                bf[ni][1] = __float_as_uint(Bs[buf][kb + tg + 4][nb + grp]);
            }
#pragma unroll
            for (int mi = 0; mi < 2; mi++)
#pragma unroll
                for (int ni = 0; ni < 8; ni++) {
                    asm volatile(
                        "mma.sync.aligned.m16n8k8.row.col.f32.tf32.tf32.f32 "
                        "{%0,%1,%2,%3}, {%4,%5,%6,%7}, {%8,%9}, {%0,%1,%2,%3};\n"
                        : "+f"(acc[mi][ni][0]), "+f"(acc[mi][ni][1]),
                          "+f"(acc[mi][ni][2]), "+f"(acc[mi][ni][3])
                        : "r"(af[mi][0]), "r"(af[mi][1]), "r"(af[mi][2]), "r"(af[mi][3]),
                          "r"(bf[ni][0]), "r"(bf[ni][1]));
                }
        }
        __syncthreads();
    }

#pragma unroll
    for (int mi = 0; mi < 2; mi++) {
        int r0 = blockRow + warp_m * 32 + mi * 16 + grp;
        int r1 = r0 + 8;
#pragma unroll
        for (int ni = 0; ni < 8; ni++) {
            int c0 = blockCol + warp_n * 64 + ni * 8 + 2 * tg;
#pragma unroll
            for (int h = 0; h < 2; h++) {
                int c = c0 + h;
                float b = bias ? bias[c] : 0.0f;
                if (r0 < M) {
                    float v = acc[mi][ni][h] + b;
                    if (doRelu) v = fmaxf(v, 0.0f);
                    if (doRound) v = tf32r(v);
                    C[(size_t)r0 * N + c] = v;
                }
                if (r1 < M) {
                    float v = acc[mi][ni][2 + h] + b;
                    if (doRelu) v = fmaxf(v, 0.0f);
                    if (doRound) v = tf32r(v);
                    C[(size_t)r1 * N + c] = v;
                }
            }
        }
    }
}

// ---------------- SLOW tf32 GEMM (edge case: emb1) ---------------------------
__global__ __launch_bounds__(256) void k_tf32gemm(
    const float* Aext, int aId,
    const float* __restrict__ B,
    const float* __restrict__ bias,
    float* Cext, int cId,
    int M, int N, int K, int doRelu, int doRound)
{
    const float* __restrict__ A = (aId >= 0) ? sel(aId) : Aext;
    float* __restrict__ C       = (cId >= 0) ? sel(cId) : Cext;

    __shared__ uint32_t As[16][132];
    __shared__ uint32_t Bs[16][132];

    const int tid  = threadIdx.x;
    const int wid  = tid >> 5;
    const int lane = tid & 31;
    const int grp  = lane >> 2;
    const int tg   = lane & 3;
    const int warp_m = wid & 1;
    const int warp_n = wid >> 1;

    const int blockRow = blockIdx.y * 128;
    const int blockCol = blockIdx.x * 128;
    const bool nAligned = ((N & 3) == 0);

    float acc[4][4][4];
#pragma unroll
    for (int mi = 0; mi < 4; mi++)
#pragma unroll
        for (int ni = 0; ni < 4; ni++)
#pragma unroll
            for (int r = 0; r < 4; r++) acc[mi][ni][r] = 0.0f;

    const int kIters = (K + 15) / 16;
    for (int it = 0; it < kIters; it++) {
        const int k0 = it * 16;
#pragma unroll
        for (int i = 0; i < 2; i++) {
            int idx = tid + i * 256;
            int row = idx >> 2;
            int c4  = (idx & 3) << 2;
            int gr = blockRow + row;
            int gk = k0 + c4;
            float v0 = 0, v1 = 0, v2 = 0, v3 = 0;
            if (gr < M) {
                const float* ap = A + (long long)gr * K + gk;
                if (gk + 3 < K) {
                    float4 v = *(const float4*)ap;
                    v0 = v.x; v1 = v.y; v2 = v.z; v3 = v.w;
                } else {
                    if (gk + 0 < K) v0 = ap[0];
                    if (gk + 1 < K) v1 = ap[1];
                    if (gk + 2 < K) v2 = ap[2];
                    if (gk + 3 < K) v3 = ap[3];
                }
            }
            As[c4 + 0][row] = f2tf(v0);
            As[c4 + 1][row] = f2tf(v1);
            As[c4 + 2][row] = f2tf(v2);
            As[c4 + 3][row] = f2tf(v3);
        }
#pragma unroll
        for (int i = 0; i < 2; i++) {
            int idx = tid + i * 256;
            int row = idx >> 5;
            int c4  = (idx & 31) << 2;
            int gk = k0 + row;
            int gc = blockCol + c4;
            float v0 = 0, v1 = 0, v2 = 0, v3 = 0;
            if (gk < K) {
                const float* bp = B + (long long)gk * N + gc;
                if (nAligned && gc + 3 < N) {
                    float4 v = *(const float4*)bp;
                    v0 = v.x; v1 = v.y; v2 = v.z; v3 = v.w;
                } else {
                    if (gc + 0 < N) v0 = bp[0];
                    if (gc + 1 < N) v1 = bp[1];
                    if (gc + 2 < N) v2 = bp[2];
                    if (gc + 3 < N) v3 = bp[3];
                }
            }
            Bs[row][c4 + 0] = f2tf(v0);
            Bs[row][c4 + 1] = f2tf(v1);
            Bs[row][c4 + 2] = f2tf(v2);
            Bs[row][c4 + 3] = f2tf(v3);
        }
        __syncthreads();

#pragma unroll
        for (int ks = 0; ks < 2; ks++) {
            const int kb = ks * 8;
            uint32_t af[4][4], bf[4][2];
#pragma unroll
            for (int mi = 0; mi < 4; mi++) {
                int rb = warp_m * 64 + mi * 16;
                af[mi][0] = As[kb + tg][rb + grp];
                af[mi][1] = As[kb + tg][rb + grp + 8];
                af[mi][2] = As[kb + tg + 4][rb + grp];
                af[mi][3] = As[kb + tg + 4][rb + grp + 8];
            }
#pragma unroll
            for (int ni = 0; ni < 4; ni++) {
                int nb = warp_n * 32 + ni * 8;
                bf[ni][0] = Bs[kb + tg][nb + grp];
                bf[ni][1] = Bs[kb + tg + 4][nb + grp];
            }
#pragma unroll
            for (int mi = 0; mi < 4; mi++)
#pragma unroll
                for (int ni = 0; ni < 4; ni++) {
                    asm volatile(
                        "mma.sync.aligned.m16n8k8.row.col.f32.tf32.tf32.f32 "
                        "{%0,%1,%2,%3}, {%4,%5,%6,%7}, {%8,%9}, {%0,%1,%2,%3};\n"
                        : "+f"(acc[mi][ni][0]), "+f"(acc[mi][ni][1]),
                          "+f"(acc[mi][ni][2]), "+f"(acc[mi][ni][3])
                        : "r"(af[mi][0]), "r"(af[mi][1]), "r"(af[mi][2]), "r"(af[mi][3]),
                          "r"(bf[ni][0]), "r"(bf[ni][1]));
                }
        }
        __syncthreads();
    }

#pragma unroll
    for (int mi = 0; mi < 4; mi++) {
        int r0 = blockRow + warp_m * 64 + mi * 16 + grp;
        int r1 = r0 + 8;
#pragma unroll
        for (int ni = 0; ni < 4; ni++) {
            int c0 = blockCol + warp_n * 32 + ni * 8 + 2 * tg;
#pragma unroll
            for (int h = 0; h < 2; h++) {
                int c = c0 + h;
                if (c >= N) continue;
                float b = bias ? bias[c] : 0.0f;
                if (r0 < M) {
                    float v = acc[mi][ni][h] + b;
                    if (doRelu) v = fmaxf(v, 0.0f);
                    if (doRound) v = tf32r(v);
                    C[(long long)r0 * N + c] = v;
                }
                if (r1 < M) {
                    float v = acc[mi][ni][2 + h] + b;
                    if (doRelu) v = fmaxf(v, 0.0f);
                    if (doRound) v = tf32r(v);
                    C[(long long)r1 * N + c] = v;
                }
            }
        }
    }
}

// ---------------- gather: out[n,:] = round(dis[n]^2 t[n,:] + sum w t[src,:]) -
__global__ void k_gather(int tId, int outId, int F4) {
    const float4* __restrict__ t4 = (const float4*)sel(tId);
    float4* __restrict__ o4       = (float4*)sel(outId);

    int node = blockIdx.x;
    int tid  = threadIdx.x;

    float d = g_dis[node];
    float sw = d * d;
    float4 v = t4[(long long)node * F4 + tid];
    float4 acc;
    acc.x = sw * v.x; acc.y = sw * v.y; acc.z = sw * v.z; acc.w = sw * v.w;

    int s = g_rowstart[node];
    int e = s + g_ecnt[node];
    for (int i = s; i < e; i++) {
        int src = g_csr_src[i];
        float w = g_csr_w[i];
        float4 u = t4[(long long)src * F4 + tid];
        acc.x += w * u.x; acc.y += w * u.y; acc.z += w * u.z; acc.w += w * u.w;
    }
    acc.x = tf32r(acc.x); acc.y = tf32r(acc.y);
    acc.z = tf32r(acc.z); acc.w = tf32r(acc.w);
    o4[(long long)node * F4 + tid] = acc;
}

// ---------------- segmented mean pooling (batch sorted), rounded ------------
__global__ void k_pool2(int hId, const void* __restrict__ batch) {
    const float* __restrict__ h = sel(hId);
    int g = blockIdx.x;
    int f = blockIdx.y * 256 + threadIdx.x;

    int lo = 0, hi = NN;
    while (lo < hi) { int mid = (lo + hi) >> 1; if (ld_idx(batch, mid) < g) lo = mid + 1; else hi = mid; }
    int start = lo;
    lo = start; hi = NN;
    while (lo < hi) { int mid = (lo + hi) >> 1; if (ld_idx(batch, mid) < g + 1) lo = mid + 1; else hi = mid; }
    int end = lo;

    float acc = 0.0f;
    for (int n = start; n < end; n++)
        acc += h[(long long)n * H1024 + f];
    float cnt = (float)(end - start);
    g_pooled[g * H1024 + f] = tf32r(acc / fmaxf(cnt, 1.0f));
}

// ---------------- head: out[g,j] = head_b[j] + dot(z[g,:], head_w[:,j]) -----
// One block per graph; z row cached in smem; weight reads fully coalesced.
__global__ __launch_bounds__(384) void k_head(const float* __restrict__ hw,
                                              const float* __restrict__ hb,
                                              float* __restrict__ out) {
    __shared__ float zs[FC];
    int g = blockIdx.x;
    for (int k = threadIdx.x; k < FC; k += blockDim.x)
        zs[k] = g_z[(size_t)g * FC + k];
    __syncthreads();
    int j = threadIdx.x;
    if (j >= NCLS) return;
    float acc = hb[j];
#pragma unroll 8
    for (int k = 0; k < FC; k++)
        acc = fmaf(zs[k], hw[(size_t)k * NCLS + j], acc);
    out[(size_t)g * NCLS + j] = acc;
}

// ---------------- host orchestration ---------------------------------------
static void fastgemm(int aId, int bOff, const float* bias, int cId,
                     int M, int N, int K, int relu, int rnd) {
    dim3 grid(N / 256, (M + 127) / 128);
    k_fastgemm<<<grid, 512, FG_SMEM>>>(aId, bOff, bias, cId, M, N, K, relu, rnd);
}
static void slowgemm(const float* Aext, int aId, const float* B, const float* bias,
                     float* Cext, int cId, int M, int N, int K, int relu, int rnd) {
    dim3 grid((N + 127) / 128, (M + 127) / 128);
    k_tf32gemm<<<grid, 256>>>(Aext, aId, B, bias, Cext, cId, M, N, K, relu, rnd);
}

extern "C" void kernel_launch(void* const* d_in, const int* in_sizes, int n_in,
                              void* d_out, int out_size) {
    const float* x         = (const float*)d_in[0];
    const float* edge_attr = (const float*)d_in[1];
    const void*  ei        = d_in[2];
    const void*  batch     = d_in[3];
    const float *emb_w1 = (const float*)d_in[4],  *emb_b1 = (const float*)d_in[5];
    const float *emb_w2 = (const float*)d_in[6],  *emb_b2 = (const float*)d_in[7];
    const float *ep_w1  = (const float*)d_in[8],  *ep_b1  = (const float*)d_in[9];
    const float *ep_w2  = (const float*)d_in[10], *ep_b2  = (const float*)d_in[11];
    const float *c6_w   = (const float*)d_in[12], *c6_b   = (const float*)d_in[13];
    const float *c7_w   = (const float*)d_in[14], *c7_b   = (const float*)d_in[15];
    const float *c8_w   = (const float*)d_in[16], *c8_b   = (const float*)d_in[17];
    const float *fc1_w  = (const float*)d_in[18], *fc1_b  = (const float*)d_in[19];
    const float *head_w = (const float*)d_in[20], *head_b = (const float*)d_in[21];
    float* out = (float*)d_out;

    cudaFuncSetAttribute(k_fastgemm, cudaFuncAttributeMaxDynamicSharedMemorySize, FG_SMEM);

    // preprocessing: dtype, weights, edge weights, CSR
    k_detect<<<1, 256>>>((const unsigned int*)ei);
    k_init<<<NB_SCAN, 256>>>();
    k_round5<<<(WR_TOTAL + 255) / 256, 256>>>(emb_w2, c6_w, c7_w, c8_w, fc1_w);
    k_edge_mlp<<<(EE + 255) / 256, 256>>>(edge_attr, ep_w1, ep_b1, ep_w2, ep_b2);
    k_degcnt<<<(EE + 255) / 256, 256>>>(ei);
    k_dis<<<NB_SCAN, 256>>>();
    k_scan_block<<<NB_SCAN, 256>>>();
    k_scan_tops<<<1, 32>>>();
    k_scan_add<<<NB_SCAN, 256>>>();
    k_fill<<<(EE + 255) / 256, 256>>>(ei);

    // embedding MLP
    slowgemm(x, -1, emb_w1, emb_b1, nullptr, BUF_C, NN, H512, FIN, 1, 1);   // -> bufC (rounded)
    fastgemm(BUF_C, W2R_OFF, emb_b2, BUF_B, NN, H512, H512, 1, 0);          // h -> bufB

    // conv1: aggregate (512) then transform
    k_gather<<<NN, H512 / 4>>>(BUF_B, BUF_C, H512 / 4);                     // agg(h) -> bufC
    fastgemm(BUF_C, C6_OFF, c6_b, BUF_A, NN, H1024, H512, 1, 0);            // h1 -> bufA

    // conv2
    k_gather<<<NN, H1024 / 4>>>(BUF_A, BUF_C, H1024 / 4);
    fastgemm(BUF_C, C7_OFF, c7_b, BUF_B, NN, H1024, H1024, 1, 0);           // h2 -> bufB

    // conv3
    k_gather<<<NN, H1024 / 4>>>(BUF_B, BUF_A, H1024 / 4);
    fastgemm(BUF_A, C8_OFF, c8_b, BUF_C, NN, H1024, H1024, 1, 0);           // h3 -> bufC

    // mean pool (rounded)
    dim3 pgrid(GG, H1024 / 256);
    k_pool2<<<pgrid, 256>>>(BUF_C, batch);

    // head
    fastgemm(BUF_POOLED, FC1_OFF, fc1_b, BUF_Z, GG, FC, H1024, 1, 0);       // z
    k_head<<<GG, 384>>>(head_w, head_b, out);
}

// round 11
// speedup vs baseline: 1.1293x; 1.1293x over previous
#include <cuda_runtime.h>
#include <cstdint>

#define NN    50000
#define EE    200000
#define GG    128
#define FIN   40
#define H512  512
#define H1024 1024
#define FC    2048
#define NCLS  345
#define NB_SCAN ((NN + 255) / 256)

// pre-rounded weight scratch offsets (floats), layout [K][N] (original)
#define W2R_OFF  0
#define C6_OFF   262144
#define C7_OFF   786432
#define C8_OFF   1835008
#define FC1_OFF  2883584
#define WR_TOTAL 4980736

// dynamic smem for fastgemm (BK=32): As[2][128][36] + Bs[2][32][264] floats
#define FG_AS_FLOATS (2 * 128 * 36)
#define FG_BS_FLOATS (2 * 32 * 264)
#define FG_SMEM ((FG_AS_FLOATS + FG_BS_FLOATS) * 4)

// ---------------- scratch (static device globals; no allocations) ----------
__device__ float g_bufA[(size_t)NN * H1024];
__device__ float g_bufB[(size_t)NN * H1024];
__device__ float g_bufC[(size_t)NN * H1024];
__device__ float g_wr[WR_TOTAL];
__device__ float g_ew[EE];
__device__ float g_deg[NN];
__device__ float g_dis[NN];
__device__ float g_pooled[GG * H1024];
__device__ float g_z[GG * FC];
__device__ int   g_is64;

// CSR (by destination)
__device__ int   g_ecnt[NN];
__device__ int   g_rowstart[NN];
__device__ int   g_next[NN];
__device__ int   g_csr_src[EE];
__device__ float g_csr_w[EE];
__device__ int   g_blksum[NB_SCAN];

#define BUF_A      0
#define BUF_B      1
#define BUF_C      2
#define BUF_POOLED 3
#define BUF_Z      4
__device__ __forceinline__ float* sel(int id) {
    switch (id) {
        case BUF_A:      return g_bufA;
        case BUF_B:      return g_bufB;
        case BUF_C:      return g_bufC;
        case BUF_POOLED: return g_pooled;
        case BUF_Z:      return g_z;
    }
    return nullptr;
}

__device__ __forceinline__ int ld_idx(const void* p, long long i) {
    return g_is64 ? (int)((const long long*)p)[i] : ((const int*)p)[i];
}

__device__ __forceinline__ uint32_t f2tf(float x) {
    uint32_t u;
    asm("cvt.rna.tf32.f32 %0, %1;" : "=r"(u) : "f"(x));
    return u;
}
__device__ __forceinline__ float tf32r(float x) {
    uint32_t u;
    asm("cvt.rna.tf32.f32 %0, %1;" : "=r"(u) : "f"(x));
    return __uint_as_float(u);
}

#define CP_ASYNC16(dst_u32, src_ptr) \
    asm volatile("cp.async.ca.shared.global [%0], [%1], 16;\n" :: "r"(dst_u32), "l"(src_ptr))
#define CP_COMMIT() asm volatile("cp.async.commit_group;\n" ::: "memory")
#define CP_WAIT0()  asm volatile("cp.async.wait_group 0;\n" ::: "memory")
#define CP_WAIT1()  asm volatile("cp.async.wait_group 1;\n" ::: "memory")

// ---------------- dtype detection ------------------------------------------
__global__ void k_detect(const unsigned int* __restrict__ ei_words) {
    __shared__ int found;
    if (threadIdx.x == 0) found = 0;
    __syncthreads();
    for (int i = 1 + 2 * threadIdx.x; i < 4096; i += 2 * blockDim.x)
        if (ei_words[i] != 0u) found = 1;
    __syncthreads();
    if (threadIdx.x == 0) g_is64 = (found ? 0 : 1);
}

__global__ void k_init() {
    int i = blockIdx.x * blockDim.x + threadIdx.x;
    if (i < NN) { g_deg[i] = 1.0f; g_ecnt[i] = 0; }
}

// ---------------- weight pre-rounding (tf32 rna, once per launch) ----------
__global__ void k_round5(const float* __restrict__ w2, const float* __restrict__ c6,
                         const float* __restrict__ c7, const float* __restrict__ c8,
                         const float* __restrict__ f1) {
    int i = blockIdx.x * 256 + threadIdx.x;
    if (i >= WR_TOTAL) return;
    float v;
    if      (i < C6_OFF)  v = w2[i - W2R_OFF];
    else if (i < C7_OFF)  v = c6[i - C6_OFF];
    else if (i < C8_OFF)  v = c7[i - C7_OFF];
    else if (i < FC1_OFF) v = c8[i - C8_OFF];
    else                  v = f1[i - FC1_OFF];
    g_wr[i] = tf32r(v);
}

// ---------------- edge MLP + weighted degree + in-edge count (fused) --------
__global__ void k_edge_mlp_deg(const float* __restrict__ ea,
                               const float* __restrict__ w1, const float* __restrict__ b1,
                               const float* __restrict__ w2, const float* __restrict__ b2,
                               const void* __restrict__ ei) {
    int e = blockIdx.x * blockDim.x + threadIdx.x;
    if (e >= EE) return;
    float a0 = ea[e * 3 + 0], a1 = ea[e * 3 + 1], a2 = ea[e * 3 + 2];
    float acc = b2[0];
#pragma unroll 8
    for (int h = 0; h < 64; h++) {
        float v = b1[h] + a0 * w1[h] + a1 * w1[64 + h] + a2 * w1[128 + h];
        acc += fmaxf(v, 0.0f) * w2[h];
    }
    float ew = 1.0f / (1.0f + expf(-acc));
    g_ew[e] = ew;
    int d = ld_idx(ei, (long long)EE + e);
    if (d >= 0 && d < NN) {
        atomicAdd(&g_deg[d], ew);
        atomicAdd(&g_ecnt[d], 1);
    }
}

__global__ void k_dis() {
    int i = blockIdx.x * blockDim.x + threadIdx.x;
    if (i >= NN) return;
    g_dis[i] = rsqrtf(g_deg[i]);
}

// ---------------- CSR build --------------------------------------------------
__global__ void k_scan_block() {
    __shared__ int s[256];
    int tid = threadIdx.x;
    int i = blockIdx.x * 256 + tid;
    int v = (i < NN) ? g_ecnt[i] : 0;
    s[tid] = v;
    __syncthreads();
#pragma unroll
    for (int off = 1; off < 256; off <<= 1) {
        int t = (tid >= off) ? s[tid - off] : 0;
        __syncthreads();
        s[tid] += t;
        __syncthreads();
    }
    if (i < NN) g_rowstart[i] = s[tid] - v;
    if (tid == 255) g_blksum[blockIdx.x] = s[tid];
}

__global__ void k_scan_tops() {
    if (threadIdx.x == 0 && blockIdx.x == 0) {
        int run = 0;
        for (int b = 0; b < NB_SCAN; b++) {
            int t = g_blksum[b];
            g_blksum[b] = run;
            run += t;
        }
    }
}

__global__ void k_scan_add() {
    int i = blockIdx.x * 256 + threadIdx.x;
    if (i >= NN) return;
    int r = g_rowstart[i] + g_blksum[blockIdx.x];
    g_rowstart[i] = r;
    g_next[i] = r;
}

__global__ void k_fill(const void* __restrict__ ei) {
    int e = blockIdx.x * blockDim.x + threadIdx.x;
    if (e >= EE) return;
    int s = ld_idx(ei, e);
    int d = ld_idx(ei, (long long)EE + e);
    if (s < 0 || s >= NN || d < 0 || d >= NN) return;
    int pos = atomicAdd(&g_next[d], 1);
    g_csr_src[pos] = s;
    g_csr_w[pos]   = g_dis[s] * g_ew[e] * g_dis[d];
}

// ---------------- FAST tf32 GEMM: cp.async, CTA 128x256, 8 warps 64x64 ------
// BK=32 (4 mma slices per sync). K%32==0, N%256==0, inputs pre-rounded.
__global__ __launch_bounds__(256) void k_fastgemm(
    int aId, int bOff, const float* __restrict__ bias, int cId,
    int M, int N, int K, int doRelu, int doRound)
{
    extern __shared__ float smemF[];
    float (*As)[128][36] = (float(*)[128][36])smemF;                    // [buf][m][k]
    float (*Bs)[32][264] = (float(*)[32][264])(smemF + FG_AS_FLOATS);   // [buf][k][n]

    const float* __restrict__ A = sel(aId);
    const float* __restrict__ B = g_wr + bOff;
    float* __restrict__ C       = sel(cId);

    const int tid  = threadIdx.x;
    const int wid  = tid >> 5;
    const int lane = tid & 31;
    const int grp  = lane >> 2;
    const int tg   = lane & 3;
    const int warp_m = wid & 1;    // 2 warps along M (64 rows)
    const int warp_n = wid >> 1;   // 4 warps along N (64 cols)

    const int blockRow = blockIdx.y * 128;
    const int blockCol = blockIdx.x * 256;

    float acc[4][8][4];
#pragma unroll
    for (int mi = 0; mi < 4; mi++)
#pragma unroll
        for (int ni = 0; ni < 8; ni++)
#pragma unroll
            for (int r = 0; r < 4; r++) acc[mi][ni][r] = 0.0f;

    const int kIters = K >> 5;

    uint32_t asB[2], bsB[2];
    asB[0] = (uint32_t)__cvta_generic_to_shared(&As[0][0][0]);
    asB[1] = (uint32_t)__cvta_generic_to_shared(&As[1][0][0]);
    bsB[0] = (uint32_t)__cvta_generic_to_shared(&Bs[0][0][0]);
    bsB[1] = (uint32_t)__cvta_generic_to_shared(&Bs[1][0][0]);

    // A: 128x32 = 1024 float4 chunks (4/thread); B: 32x256 = 2048 chunks (8/thread)
    auto load_tile = [&](int it, int buf) {
        const int k0 = it << 5;
#pragma unroll
        for (int i = 0; i < 4; i++) {
            int q = tid + i * 256;
            int row = q >> 3;              // 0..127
            int c4  = (q & 7) << 2;        // 0..28
            int gr = min(blockRow + row, M - 1);
            CP_ASYNC16(asB[buf] + (row * 36 + c4) * 4, A + (size_t)gr * K + k0 + c4);
        }
#pragma unroll
        for (int i = 0; i < 8; i++) {
            int q = tid + i * 256;
            int br = q >> 6;               // 0..31
            int bn = (q & 63) << 2;        // 0..252
            CP_ASYNC16(bsB[buf] + (br * 264 + bn) * 4, B + (size_t)(k0 + br) * N + blockCol + bn);
        }
        CP_COMMIT();
    };

    load_tile(0, 0);

    for (int it = 0; it < kIters; it++) {
        const int buf = it & 1;
        if (it + 1 < kIters) {
            load_tile(it + 1, buf ^ 1);
            CP_WAIT1();
        } else {
            CP_WAIT0();
        }
        __syncthreads();

#pragma unroll
        for (int ks = 0; ks < 4; ks++) {
            const int kb = ks * 8;
            uint32_t af[4][4], bf[8][2];
#pragma unroll
            for (int mi = 0; mi < 4; mi++) {
                int rb = warp_m * 64 + mi * 16;
                af[mi][0] = __float_as_uint(As[buf][rb + grp][kb + tg]);
                af[mi][1] = __float_as_uint(As[buf][rb + grp + 8][kb + tg]);
                af[mi][2] = __float_as_uint(As[buf][rb + grp][kb + tg + 4]);
                af[mi][3] = __float_as_uint(As[buf][rb + grp + 8][kb + tg + 4]);
            }
#pragma unroll
            for (int ni = 0; ni < 8; ni++) {
                int nb = warp_n * 64 + ni * 8;
                bf[ni][0] = __float_as_uint(Bs[buf][kb + tg][nb + grp]);
                bf[ni][1] = __float_as_uint(Bs[buf][kb + tg + 4][nb + grp]);
            }
#pragma unroll
            for (int mi = 0; mi < 4; mi++)
#pragma unroll
                for (int ni = 0; ni < 8; ni++) {
                    asm volatile(
                        "mma.sync.aligned.m16n8k8.row.col.f32.tf32.tf32.f32 "
                        "{%0,%1,%2,%3}, {%4,%5,%6,%7}, {%8,%9}, {%0,%1,%2,%3};\n"
                        : "+f"(acc[mi][ni][0]), "+f"(acc[mi][ni][1]),
                          "+f"(acc[mi][ni][2]), "+f"(acc[mi][ni][3])
                        : "r"(af[mi][0]), "r"(af[mi][1]), "r"(af[mi][2]), "r"(af[mi][3]),
                          "r"(bf[ni][0]), "r"(bf[ni][1]));
                }
        }
        __syncthreads();
    }

#pragma unroll
    for (int mi = 0; mi < 4; mi++) {
        int r0 = blockRow + warp_m * 64 + mi * 16 + grp;
        int r1 = r0 + 8;
#pragma unroll
        for (int ni = 0; ni < 8; ni++) {
            int c0 = blockCol + warp_n * 64 + ni * 8 + 2 * tg;
#pragma unroll
            for (int h = 0; h < 2; h++) {
                int c = c0 + h;
                float b = bias ? bias[c] : 0.0f;
                if (r0 < M) {
                    float v = acc[mi][ni][h] + b;
                    if (doRelu) v = fmaxf(v, 0.0f);
                    if (doRound) v = tf32r(v);
                    C[(size_t)r0 * N + c] = v;
                }
                if (r1 < M) {
                    float v = acc[mi][ni][2 + h] + b;
                    if (doRelu) v = fmaxf(v, 0.0f);
                    if (doRound) v = tf32r(v);
                    C[(size_t)r1 * N + c] = v;
                }
            }
        }
    }
}

// ---------------- SLOW tf32 GEMM (edge case: emb1) ---------------------------
__global__ __launch_bounds__(256) void k_tf32gemm(
    const float* Aext, int aId,
    const float* __restrict__ B,
    const float* __restrict__ bias,
    float* Cext, int cId,
    int M, int N, int K, int doRelu, int doRound)
{
    const float* __restrict__ A = (aId >= 0) ? sel(aId) : Aext;
    float* __restrict__ C       = (cId >= 0) ? sel(cId) : Cext;

    __shared__ uint32_t As[16][132];
    __shared__ uint32_t Bs[16][132];

    const int tid  = threadIdx.x;
    const int wid  = tid >> 5;
    const int lane = tid & 31;
    const int grp  = lane >> 2;
    const int tg   = lane & 3;
    const int warp_m = wid & 1;
    const int warp_n = wid >> 1;

    const int blockRow = blockIdx.y * 128;
    const int blockCol = blockIdx.x * 128;
    const bool nAligned = ((N & 3) == 0);

    float acc[4][4][4];
#pragma unroll
    for (int mi = 0; mi < 4; mi++)
#pragma unroll
        for (int ni = 0; ni < 4; ni++)
#pragma unroll
            for (int r = 0; r < 4; r++) acc[mi][ni][r] = 0.0f;

    const int kIters = (K + 15) / 16;
    for (int it = 0; it < kIters; it++) {
        const int k0 = it * 16;
#pragma unroll
        for (int i = 0; i < 2; i++) {
            int idx = tid + i * 256;
            int row = idx >> 2;
            int c4  = (idx & 3) << 2;
            int gr = blockRow + row;
            int gk = k0 + c4;
            float v0 = 0, v1 = 0, v2 = 0, v3 = 0;
            if (gr < M) {
                const float* ap = A + (long long)gr * K + gk;
                if (gk + 3 < K) {
                    float4 v = *(const float4*)ap;
                    v0 = v.x; v1 = v.y; v2 = v.z; v3 = v.w;
                } else {
                    if (gk + 0 < K) v0 = ap[0];
                    if (gk + 1 < K) v1 = ap[1];
                    if (gk + 2 < K) v2 = ap[2];
                    if (gk + 3 < K) v3 = ap[3];
                }
            }
            As[c4 + 0][row] = f2tf(v0);
            As[c4 + 1][row] = f2tf(v1);
            As[c4 + 2][row] = f2tf(v2);
            As[c4 + 3][row] = f2tf(v3);
        }
#pragma unroll
        for (int i = 0; i < 2; i++) {
            int idx = tid + i * 256;
            int row = idx >> 5;
            int c4  = (idx & 31) << 2;
            int gk = k0 + row;
            int gc = blockCol + c4;
            float v0 = 0, v1 = 0, v2 = 0, v3 = 0;
            if (gk < K) {
                const float* bp = B + (long long)gk * N + gc;
                if (nAligned && gc + 3 < N) {
                    float4 v = *(const float4*)bp;
                    v0 = v.x; v1 = v.y; v2 = v.z; v3 = v.w;
                } else {
                    if (gc + 0 < N) v0 = bp[0];
                    if (gc + 1 < N) v1 = bp[1];
                    if (gc + 2 < N) v2 = bp[2];
                    if (gc + 3 < N) v3 = bp[3];
                }
            }
            Bs[row][c4 + 0] = f2tf(v0);
            Bs[row][c4 + 1] = f2tf(v1);
            Bs[row][c4 + 2] = f2tf(v2);
            Bs[row][c4 + 3] = f2tf(v3);
        }
        __syncthreads();

#pragma unroll
        for (int ks = 0; ks < 2; ks++) {
            const int kb = ks * 8;
            uint32_t af[4][4], bf[4][2];
#pragma unroll
            for (int mi = 0; mi < 4; mi++) {
                int rb = warp_m * 64 + mi * 16;
                af[mi][0] = As[kb + tg][rb + grp];
                af[mi][1] = As[kb + tg][rb + grp + 8];
                af[mi][2] = As[kb + tg + 4][rb + grp];
                af[mi][3] = As[kb + tg + 4][rb + grp + 8];
            }
#pragma unroll
            for (int ni = 0; ni < 4; ni++) {
                int nb = warp_n * 32 + ni * 8;
                bf[ni][0] = Bs[kb + tg][nb + grp];
                bf[ni][1] = Bs[kb + tg + 4][nb + grp];
            }
#pragma unroll
            for (int mi = 0; mi < 4; mi++)
#pragma unroll
                for (int ni = 0; ni < 4; ni++) {
                    asm volatile(
                        "mma.sync.aligned.m16n8k8.row.col.f32.tf32.tf32.f32 "
                        "{%0,%1,%2,%3}, {%4,%5,%6,%7}, {%8,%9}, {%0,%1,%2,%3};\n"
                        : "+f"(acc[mi][ni][0]), "+f"(acc[mi][ni][1]),
                          "+f"(acc[mi][ni][2]), "+f"(acc[mi][ni][3])
                        : "r"(af[mi][0]), "r"(af[mi][1]), "r"(af[mi][2]), "r"(af[mi][3]),
                          "r"(bf[ni][0]), "r"(bf[ni][1]));
                }
        }
        __syncthreads();
    }

#pragma unroll
    for (int mi = 0; mi < 4; mi++) {
        int r0 = blockRow + warp_m * 64 + mi * 16 + grp;
        int r1 = r0 + 8;
#pragma unroll
        for (int ni = 0; ni < 4; ni++) {
            int c0 = blockCol + warp_n * 32 + ni * 8 + 2 * tg;
#pragma unroll
            for (int h = 0; h < 2; h++) {
                int c = c0 + h;
                if (c >= N) continue;
                float b = bias ? bias[c] : 0.0f;
                if (r0 < M) {
                    float v = acc[mi][ni][h] + b;
                    if (doRelu) v = fmaxf(v, 0.0f);
                    if (doRound) v = tf32r(v);
                    C[(long long)r0 * N + c] = v;
                }
                if (r1 < M) {
                    float v = acc[mi][ni][2 + h] + b;
                    if (doRelu) v = fmaxf(v, 0.0f);
                    if (doRound) v = tf32r(v);
                    C[(long long)r1 * N + c] = v;
                }
            }
        }
    }
}

// ---------------- gather: out[n,:] = round(dis[n]^2 t[n,:] + sum w t[src,:]) -
__global__ void k_gather(int tId, int outId, int F4) {
    const float4* __restrict__ t4 = (const float4*)sel(tId);
    float4* __restrict__ o4       = (float4*)sel(outId);

    int node = blockIdx.x;
    int tid  = threadIdx.x;

    float d = g_dis[node];
    float sw = d * d;
    float4 v = t4[(long long)node * F4 + tid];
    float4 acc;
    acc.x = sw * v.x; acc.y = sw * v.y; acc.z = sw * v.z; acc.w = sw * v.w;

    int s = g_rowstart[node];
    int e = s + g_ecnt[node];
    for (int i = s; i < e; i++) {
        int src = g_csr_src[i];
        float w = g_csr_w[i];
        float4 u = t4[(long long)src * F4 + tid];
        acc.x += w * u.x; acc.y += w * u.y; acc.z += w * u.z; acc.w += w * u.w;
    }
    acc.x = tf32r(acc.x); acc.y = tf32r(acc.y);
    acc.z = tf32r(acc.z); acc.w = tf32r(acc.w);
    o4[(long long)node * F4 + tid] = acc;
}

// ---------------- segmented mean pooling (batch sorted), rounded ------------
__global__ void k_pool2(int hId, const void* __restrict__ batch) {
    const float* __restrict__ h = sel(hId);
    int g = blockIdx.x;
    int f = blockIdx.y * 256 + threadIdx.x;

    int lo = 0, hi = NN;
    while (lo < hi) { int mid = (lo + hi) >> 1; if (ld_idx(batch, mid) < g) lo = mid + 1; else hi = mid; }
    int start = lo;
    lo = start; hi = NN;
    while (lo < hi) { int mid = (lo + hi) >> 1; if (ld_idx(batch, mid) < g + 1) lo = mid + 1; else hi = mid; }
    int end = lo;

    float acc = 0.0f;
    for (int n = start; n < end; n++)
        acc += h[(long long)n * H1024 + f];
    float cnt = (float)(end - start);
    g_pooled[g * H1024 + f] = tf32r(acc / fmaxf(cnt, 1.0f));
}

// ---------------- head: out[g,j] = head_b[j] + dot(z[g,:], head_w[:,j]) -----
__global__ __launch_bounds__(384) void k_head(const float* __restrict__ hw,
                                              const float* __restrict__ hb,
                                              float* __restrict__ out) {
    __shared__ float zs[FC];
    int g = blockIdx.x;
    for (int k = threadIdx.x; k < FC; k += blockDim.x)
        zs[k] = g_z[(size_t)g * FC + k];
    __syncthreads();
    int j = threadIdx.x;
    if (j >= NCLS) return;
    float acc = hb[j];
#pragma unroll 8
    for (int k = 0; k < FC; k++)
        acc = fmaf(zs[k], hw[(size_t)k * NCLS + j], acc);
    out[(size_t)g * NCLS + j] = acc;
}

// ---------------- host orchestration ---------------------------------------
static void fastgemm(int aId, int bOff, const float* bias, int cId,
                     int M, int N, int K, int relu, int rnd) {
    dim3 grid(N / 256, (M + 127) / 128);
    k_fastgemm<<<grid, 256, FG_SMEM>>>(aId, bOff, bias, cId, M, N, K, relu, rnd);
}
static void slowgemm(const float* Aext, int aId, const float* B, const float* bias,
                     float* Cext, int cId, int M, int N, int K, int relu, int rnd) {
    dim3 grid((N + 127) / 128, (M + 127) / 128);
    k_tf32gemm<<<grid, 256>>>(Aext, aId, B, bias, Cext, cId, M, N, K, relu, rnd);
}

extern "C" void kernel_launch(void* const* d_in, const int* in_sizes, int n_in,
                              void* d_out, int out_size) {
    const float* x         = (const float*)d_in[0];
    const float* edge_attr = (const float*)d_in[1];
    const void*  ei        = d_in[2];
    const void*  batch     = d_in[3];
    const float *emb_w1 = (const float*)d_in[4],  *emb_b1 = (const float*)d_in[5];
    const float *emb_w2 = (const float*)d_in[6],  *emb_b2 = (const float*)d_in[7];
    const float *ep_w1  = (const float*)d_in[8],  *ep_b1  = (const float*)d_in[9];
    const float *ep_w2  = (const float*)d_in[10], *ep_b2  = (const float*)d_in[11];
    const float *c6_w   = (const float*)d_in[12], *c6_b   = (const float*)d_in[13];
    const float *c7_w   = (const float*)d_in[14], *c7_b   = (const float*)d_in[15];
    const float *c8_w   = (const float*)d_in[16], *c8_b   = (const float*)d_in[17];
    const float *fc1_w  = (const float*)d_in[18], *fc1_b  = (const float*)d_in[19];
    const float *head_w = (const float*)d_in[20], *head_b = (const float*)d_in[21];
    float* out = (float*)d_out;

    cudaFuncSetAttribute(k_fastgemm, cudaFuncAttributeMaxDynamicSharedMemorySize, FG_SMEM);

    // preprocessing: dtype, weights, edge weights + degree, CSR
    k_detect<<<1, 256>>>((const unsigned int*)ei);
    k_init<<<NB_SCAN, 256>>>();
    k_round5<<<(WR_TOTAL + 255) / 256, 256>>>(emb_w2, c6_w, c7_w, c8_w, fc1_w);
    k_edge_mlp_deg<<<(EE + 255) / 256, 256>>>(edge_attr, ep_w1, ep_b1, ep_w2, ep_b2, ei);
    k_dis<<<NB_SCAN, 256>>>();
    k_scan_block<<<NB_SCAN, 256>>>();
    k_scan_tops<<<1, 32>>>();
    k_scan_add<<<NB_SCAN, 256>>>();
    k_fill<<<(EE + 255) / 256, 256>>>(ei);

    // embedding MLP
    slowgemm(x, -1, emb_w1, emb_b1, nullptr, BUF_C, NN, H512, FIN, 1, 1);   // -> bufC (rounded)
    fastgemm(BUF_C, W2R_OFF, emb_b2, BUF_B, NN, H512, H512, 1, 0);          // h -> bufB

    // conv1: aggregate (512) then transform
    k_gather<<<NN, H512 / 4>>>(BUF_B, BUF_C, H512 / 4);                     // agg(h) -> bufC
    fastgemm(BUF_C, C6_OFF, c6_b, BUF_A, NN, H1024, H512, 1, 0);            // h1 -> bufA

    // conv2
    k_gather<<<NN, H1024 / 4>>>(BUF_A, BUF_C, H1024 / 4);
    fastgemm(BUF_C, C7_OFF, c7_b, BUF_B, NN, H1024, H1024, 1, 0);           // h2 -> bufB

    // conv3
    k_gather<<<NN, H1024 / 4>>>(BUF_B, BUF_A, H1024 / 4);
    fastgemm(BUF_A, C8_OFF, c8_b, BUF_C, NN, H1024, H1024, 1, 0);           // h3 -> bufC

    // mean pool (rounded)
    dim3 pgrid(GG, H1024 / 256);
    k_pool2<<<pgrid, 256>>>(BUF_C, batch);

    // head
    fastgemm(BUF_POOLED, FC1_OFF, fc1_b, BUF_Z, GG, FC, H1024, 1, 0);       // z
    k_head<<<GG, 384>>>(head_w, head_b, out);
}

// round 12
// speedup vs baseline: 1.6813x; 1.4889x over previous
#include <cuda_runtime.h>
#include <cuda_fp16.h>
#include <cstdint>

#define NN    50000
#define EE    200000
#define GG    128
#define FIN   40
#define H512  512
#define H1024 1024
#define FC    2048
#define NCLS  345
#define NB_SCAN ((NN + 255) / 256)

// fp16 transposed weight scratch offsets (halves); layout [N][Kpad]
#define W1_OFF   0
#define W2_OFF   32768
#define C6_OFF   294912
#define C7_OFF   819200
#define C8_OFF   1867776
#define FC1_OFF  2916352
#define WH_TOTAL 5013504

// dynamic smem: As[2][128][40] + Bs[2][256][40] halves
#define AS_HALFS (2 * 128 * 40)
#define BS_HALFS (2 * 256 * 40)
#define FG_SMEM ((AS_HALFS + BS_HALFS) * 2)

// ---------------- scratch (static device globals; no allocations) ----------
__device__ __half g_bufA[(size_t)NN * H1024];
__device__ __half g_bufB[(size_t)NN * H1024];
__device__ __half g_bufC[(size_t)NN * H1024];
__device__ __half g_wh[WH_TOTAL];
__device__ __half g_pooled[GG * H1024];
__device__ __half g_z[GG * FC];
__device__ float g_ew[EE];
__device__ float g_deg[NN];
__device__ float g_dis[NN];
__device__ int   g_is64;

// CSR (by destination)
__device__ int   g_ecnt[NN];
__device__ int   g_rowstart[NN];
__device__ int   g_next[NN];
__device__ int   g_csr_src[EE];
__device__ float g_csr_w[EE];
__device__ int   g_blksum[NB_SCAN];

#define BUF_A      0
#define BUF_B      1
#define BUF_C      2
#define BUF_POOLED 3
#define BUF_Z      4
__device__ __forceinline__ __half* sel(int id) {
    switch (id) {
        case BUF_A:      return g_bufA;
        case BUF_B:      return g_bufB;
        case BUF_C:      return g_bufC;
        case BUF_POOLED: return g_pooled;
        case BUF_Z:      return g_z;
    }
    return nullptr;
}

__device__ __forceinline__ int ld_idx(const void* p, long long i) {
    return g_is64 ? (int)((const long long*)p)[i] : ((const int*)p)[i];
}

#define CP_ASYNC16(dst_u32, src_ptr) \
    asm volatile("cp.async.ca.shared.global [%0], [%1], 16;\n" :: "r"(dst_u32), "l"(src_ptr))
#define CP_COMMIT() asm volatile("cp.async.commit_group;\n" ::: "memory")
#define CP_WAIT0()  asm volatile("cp.async.wait_group 0;\n" ::: "memory")

// ---------------- dtype detection ------------------------------------------
__global__ void k_detect(const unsigned int* __restrict__ ei_words) {
    __shared__ int found;
    if (threadIdx.x == 0) found = 0;
    __syncthreads();
    for (int i = 1 + 2 * threadIdx.x; i < 4096; i += 2 * blockDim.x)
        if (ei_words[i] != 0u) found = 1;
    __syncthreads();
    if (threadIdx.x == 0) g_is64 = (found ? 0 : 1);
}

__global__ void k_init() {
    int i = blockIdx.x * blockDim.x + threadIdx.x;
    if (i < NN) { g_deg[i] = 1.0f; g_ecnt[i] = 0; }
}

// ---------------- weight transpose + fp16 convert ---------------------------
// src [K][N] fp32 -> g_wh[off + n*Kpad + k] fp16, zero-padded K..Kpad
__global__ void k_wt(const float* __restrict__ src, int off, int K, int Kpad, int N) {
    int i = blockIdx.x * 256 + threadIdx.x;
    if (i >= N * Kpad) return;
    int n = i / Kpad, k = i - n * Kpad;
    float v = (k < K) ? src[(size_t)k * N + n] : 0.0f;
    g_wh[off + i] = __float2half_rn(v);
}

// ---------------- pad x: [NN][40] fp32 -> bufA [NN][64] fp16 ----------------
__global__ void k_padx(const float* __restrict__ x) {
    int i = blockIdx.x * 256 + threadIdx.x;
    if (i >= NN * 64) return;
    int row = i >> 6, c = i & 63;
    float v = (c < FIN) ? x[(size_t)row * FIN + c] : 0.0f;
    g_bufA[i] = __float2half_rn(v);
}

// ---------------- edge MLP + weighted degree + in-edge count (fused) --------
__global__ void k_edge_mlp_deg(const float* __restrict__ ea,
                               const float* __restrict__ w1, const float* __restrict__ b1,
                               const float* __restrict__ w2, const float* __restrict__ b2,
                               const void* __restrict__ ei) {
    int e = blockIdx.x * blockDim.x + threadIdx.x;
    if (e >= EE) return;
    float a0 = ea[e * 3 + 0], a1 = ea[e * 3 + 1], a2 = ea[e * 3 + 2];
    float acc = b2[0];
#pragma unroll 8
    for (int h = 0; h < 64; h++) {
        float v = b1[h] + a0 * w1[h] + a1 * w1[64 + h] + a2 * w1[128 + h];
        acc += fmaxf(v, 0.0f) * w2[h];
    }
    float ew = 1.0f / (1.0f + expf(-acc));
    g_ew[e] = ew;
    int d = ld_idx(ei, (long long)EE + e);
    if (d >= 0 && d < NN) {
        atomicAdd(&g_deg[d], ew);
        atomicAdd(&g_ecnt[d], 1);
    }
}

__global__ void k_dis() {
    int i = blockIdx.x * blockDim.x + threadIdx.x;
    if (i >= NN) return;
    g_dis[i] = rsqrtf(g_deg[i]);
}

// ---------------- CSR build --------------------------------------------------
__global__ void k_scan_block() {
    __shared__ int s[256];
    int tid = threadIdx.x;
    int i = blockIdx.x * 256 + tid;
    int v = (i < NN) ? g_ecnt[i] : 0;
    s[tid] = v;
    __syncthreads();
#pragma unroll
    for (int off = 1; off < 256; off <<= 1) {
        int t = (tid >= off) ? s[tid - off] : 0;
        __syncthreads();
        s[tid] += t;
        __syncthreads();
    }
    if (i < NN) g_rowstart[i] = s[tid] - v;
    if (tid == 255) g_blksum[blockIdx.x] = s[tid];
}

__global__ void k_scan_tops() {
    if (threadIdx.x == 0 && blockIdx.x == 0) {
        int run = 0;
        for (int b = 0; b < NB_SCAN; b++) {
            int t = g_blksum[b];
            g_blksum[b] = run;
            run += t;
        }
    }
}

__global__ void k_scan_add() {
    int i = blockIdx.x * 256 + threadIdx.x;
    if (i >= NN) return;
    int r = g_rowstart[i] + g_blksum[blockIdx.x];
    g_rowstart[i] = r;
    g_next[i] = r;
}

__global__ void k_fill(const void* __restrict__ ei) {
    int e = blockIdx.x * blockDim.x + threadIdx.x;
    if (e >= EE) return;
    int s = ld_idx(ei, e);
    int d = ld_idx(ei, (long long)EE + e);
    if (s < 0 || s >= NN || d < 0 || d >= NN) return;
    int pos = atomicAdd(&g_next[d], 1);
    g_csr_src[pos] = s;
    g_csr_w[pos]   = g_dis[s] * g_ew[e] * g_dis[d];
}

// ---------------- FAST fp16 GEMM: cp.async, CTA 128x256, 8 warps 64x64 ------
// BK=32, mma.m16n8k16.f16 with fp32 accum. K%32==0, N%256==0.
// A fp16 [M][K]; B = g_wh+bOff fp16 [N][K]; C fp16 [M][N]; bias fp32 + relu.
__global__ __launch_bounds__(256) void k_fastgemm(
    int aId, int bOff, const float* __restrict__ bias, int cId,
    int M, int N, int K, int doRelu)
{
    extern __shared__ __half smemH[];
    __half* AsBase = smemH;                 // [2][128][40]
    __half* BsBase = smemH + AS_HALFS;      // [2][256][40]

    const __half* __restrict__ A = sel(aId);
    const __half* __restrict__ B = g_wh + bOff;
    __half* __restrict__ C       = sel(cId);

    const int tid  = threadIdx.x;
    const int wid  = tid >> 5;
    const int lane = tid & 31;
    const int grp  = lane >> 2;
    const int tg   = lane & 3;
    const int warp_m = wid & 1;    // 2 warps along M (64 rows)
    const int warp_n = wid >> 1;   // 4 warps along N (64 cols)

    const int blockRow = blockIdx.y * 128;
    const int blockCol = blockIdx.x * 256;

    float acc[4][8][4];
#pragma unroll
    for (int mi = 0; mi < 4; mi++)
#pragma unroll
        for (int ni = 0; ni < 8; ni++)
#pragma unroll
            for (int r = 0; r < 4; r++) acc[mi][ni][r] = 0.0f;

    const int T = K >> 5;

    uint32_t asB[2], bsB[2];
    asB[0] = (uint32_t)__cvta_generic_to_shared(AsBase);
    asB[1] = asB[0] + 128 * 40 * 2;
    bsB[0] = (uint32_t)__cvta_generic_to_shared(BsBase);
    bsB[1] = bsB[0] + 256 * 40 * 2;

    // A tile: 128 rows x 64B = 512 chunks (2/thread); B: 256 rows x 64B = 1024 (4/thread)
    auto load_tile = [&](int it, int buf) {
        const int k0 = it << 5;
#pragma unroll
        for (int i = 0; i < 2; i++) {
            int q = tid + i * 256;
            int row = q >> 2, c = q & 3;
            int gr = min(blockRow + row, M - 1);
            CP_ASYNC16(asB[buf] + row * 80 + c * 16, A + (size_t)gr * K + k0 + c * 8);
        }
#pragma unroll
        for (int i = 0; i < 4; i++) {
            int q = tid + i * 256;
            int row = q >> 2, c = q & 3;
            CP_ASYNC16(bsB[buf] + row * 80 + c * 16, B + (size_t)(blockCol + row) * K + k0 + c * 8);
        }
        CP_COMMIT();
    };

    load_tile(0, 0);

    for (int it = 0; it < T; it++) {
        const int buf = it & 1;
        CP_WAIT0();
        __syncthreads();   // tile data visible; everyone done reading buf^1
        if (it + 1 < T) load_tile(it + 1, buf ^ 1);

        const __half* Ab = AsBase + buf * 128 * 40;
        const __half* Bb = BsBase + buf * 256 * 40;
#pragma unroll
        for (int ks = 0; ks < 2; ks++) {
            const int kb = ks * 16;
            uint32_t af[4][4], bf[8][2];
#pragma unroll
            for (int mi = 0; mi < 4; mi++) {
                int rb = warp_m * 64 + mi * 16;
                af[mi][0] = *(const uint32_t*)&Ab[(rb + grp) * 40 + kb + 2 * tg];
                af[mi][1] = *(const uint32_t*)&Ab[(rb + grp + 8) * 40 + kb + 2 * tg];
                af[mi][2] = *(const uint32_t*)&Ab[(rb + grp) * 40 + kb + 2 * tg + 8];
                af[mi][3] = *(const uint32_t*)&Ab[(rb + grp + 8) * 40 + kb + 2 * tg + 8];
            }
#pragma unroll
            for (int ni = 0; ni < 8; ni++) {
                int nb = warp_n * 64 + ni * 8;
                bf[ni][0] = *(const uint32_t*)&Bb[(nb + grp) * 40 + kb + 2 * tg];
                bf[ni][1] = *(const uint32_t*)&Bb[(nb + grp) * 40 + kb + 2 * tg + 8];
            }
#pragma unroll
            for (int mi = 0; mi < 4; mi++)
#pragma unroll
                for (int ni = 0; ni < 8; ni++) {
                    asm volatile(
                        "mma.sync.aligned.m16n8k16.row.col.f32.f16.f16.f32 "
                        "{%0,%1,%2,%3}, {%4,%5,%6,%7}, {%8,%9}, {%0,%1,%2,%3};\n"
                        : "+f"(acc[mi][ni][0]), "+f"(acc[mi][ni][1]),
                          "+f"(acc[mi][ni][2]), "+f"(acc[mi][ni][3])
                        : "r"(af[mi][0]), "r"(af[mi][1]), "r"(af[mi][2]), "r"(af[mi][3]),
                          "r"(bf[ni][0]), "r"(bf[ni][1]));
                }
        }
    }

#pragma unroll
    for (int mi = 0; mi < 4; mi++) {
        int r0 = blockRow + warp_m * 64 + mi * 16 + grp;
        int r1 = r0 + 8;
#pragma unroll
        for (int ni = 0; ni < 8; ni++) {
            int c0 = blockCol + warp_n * 64 + ni * 8 + 2 * tg;
            float b0 = bias[c0], b1 = bias[c0 + 1];
            if (r0 < M) {
                float v0 = acc[mi][ni][0] + b0;
                float v1 = acc[mi][ni][1] + b1;
                if (doRelu) { v0 = fmaxf(v0, 0.0f); v1 = fmaxf(v1, 0.0f); }
                *(__half2*)(C + (size_t)r0 * N + c0) = __floats2half2_rn(v0, v1);
            }
            if (r1 < M) {
                float v0 = acc[mi][ni][2] + b0;
                float v1 = acc[mi][ni][3] + b1;
                if (doRelu) { v0 = fmaxf(v0, 0.0f); v1 = fmaxf(v1, 0.0f); }
                *(__half2*)(C + (size_t)r1 * N + c0) = __floats2half2_rn(v0, v1);
            }
        }
    }
}

// ---------------- gather: out[n,:] = h2(dis^2 t[n,:] + sum w t[src,:]) -------
// blockDim = F/4 threads; each thread handles 4 halves (uint2).
__global__ void k_gather(int tId, int outId, int Fq) {
    const uint2* __restrict__ t2 = (const uint2*)sel(tId);
    uint2* __restrict__ o2       = (uint2*)sel(outId);

    int node = blockIdx.x;
    int tid  = threadIdx.x;

    float d = g_dis[node];
    float sw = d * d;
    uint2 u = t2[(size_t)node * Fq + tid];
    const __half2* uh = (const __half2*)&u;
    float2 p0 = __half22float2(uh[0]);
    float2 p1 = __half22float2(uh[1]);
    float a0 = sw * p0.x, a1 = sw * p0.y, a2 = sw * p1.x, a3 = sw * p1.y;

    int s = g_rowstart[node];
    int e = s + g_ecnt[node];
    for (int i = s; i < e; i++) {
        int src = g_csr_src[i];
        float w = g_csr_w[i];
        uint2 v = t2[(size_t)src * Fq + tid];
        const __half2* vh = (const __half2*)&v;
        float2 q0 = __half22float2(vh[0]);
        float2 q1 = __half22float2(vh[1]);
        a0 += w * q0.x; a1 += w * q0.y; a2 += w * q1.x; a3 += w * q1.y;
    }
    uint2 o;
    ((__half2*)&o)[0] = __floats2half2_rn(a0, a1);
    ((__half2*)&o)[1] = __floats2half2_rn(a2, a3);
    o2[(size_t)node * Fq + tid] = o;
}

// ---------------- segmented mean pooling (batch sorted) ----------------------
__global__ void k_pool2(int hId, const void* __restrict__ batch) {
    const __half* __restrict__ h = sel(hId);
    int g = blockIdx.x;
    int f = blockIdx.y * 256 + threadIdx.x;

    int lo = 0, hi = NN;
    while (lo < hi) { int mid = (lo + hi) >> 1; if (ld_idx(batch, mid) < g) lo = mid + 1; else hi = mid; }
    int start = lo;
    lo = start; hi = NN;
    while (lo < hi) { int mid = (lo + hi) >> 1; if (ld_idx(batch, mid) < g + 1) lo = mid + 1; else hi = mid; }
    int end = lo;

    float acc = 0.0f;
    for (int n = start; n < end; n++)
        acc += __half2float(h[(size_t)n * H1024 + f]);
    float cnt = (float)(end - start);
    g_pooled[g * H1024 + f] = __float2half_rn(acc / fmaxf(cnt, 1.0f));
}

// ---------------- head: out[g,j] = head_b[j] + dot(z[g,:], head_w[:,j]) -----
__global__ __launch_bounds__(384) void k_head(const float* __restrict__ hw,
                                              const float* __restrict__ hb,
                                              float* __restrict__ out) {
    __shared__ float zs[FC];
    int g = blockIdx.x;
    for (int k = threadIdx.x; k < FC; k += blockDim.x)
        zs[k] = __half2float(g_z[(size_t)g * FC + k]);
    __syncthreads();
    int j = threadIdx.x;
    if (j >= NCLS) return;
    float acc = hb[j];
#pragma unroll 8
    for (int k = 0; k < FC; k++)
        acc = fmaf(zs[k], hw[(size_t)k * NCLS + j], acc);
    out[(size_t)g * NCLS + j] = acc;
}

// ---------------- host orchestration ---------------------------------------
static void fastgemm(int aId, int bOff, const float* bias, int cId,
                     int M, int N, int K, int relu) {
    dim3 grid(N / 256, (M + 127) / 128);
    k_fastgemm<<<grid, 256, FG_SMEM>>>(aId, bOff, bias, cId, M, N, K, relu);
}

extern "C" void kernel_launch(void* const* d_in, const int* in_sizes, int n_in,
                              void* d_out, int out_size) {
    const float* x         = (const float*)d_in[0];
    const float* edge_attr = (const float*)d_in[1];
    const void*  ei        = d_in[2];
    const void*  batch     = d_in[3];
    const float *emb_w1 = (const float*)d_in[4],  *emb_b1 = (const float*)d_in[5];
    const float *emb_w2 = (const float*)d_in[6],  *emb_b2 = (const float*)d_in[7];
    const float *ep_w1  = (const float*)d_in[8],  *ep_b1  = (const float*)d_in[9];
    const float *ep_w2  = (const float*)d_in[10], *ep_b2  = (const float*)d_in[11];
    const float *c6_w   = (const float*)d_in[12], *c6_b   = (const float*)d_in[13];
    const float *c7_w   = (const float*)d_in[14], *c7_b   = (const float*)d_in[15];
    const float *c8_w   = (const float*)d_in[16], *c8_b   = (const float*)d_in[17];
    const float *fc1_w  = (const float*)d_in[18], *fc1_b  = (const float*)d_in[19];
    const float *head_w = (const float*)d_in[20], *head_b = (const float*)d_in[21];
    float* out = (float*)d_out;

    cudaFuncSetAttribute(k_fastgemm, cudaFuncAttributeMaxDynamicSharedMemorySize, FG_SMEM);

    // preprocessing: dtype, pad x, fp16 weights, edge weights + degree, CSR
    k_detect<<<1, 256>>>((const unsigned int*)ei);
    k_init<<<NB_SCAN, 256>>>();
    k_padx<<<(NN * 64 + 255) / 256, 256>>>(x);
    k_wt<<<(H512 * 64 + 255) / 256, 256>>>(emb_w1, W1_OFF, FIN, 64, H512);
    k_wt<<<(H512 * H512 + 255) / 256, 256>>>(emb_w2, W2_OFF, H512, H512, H512);
    k_wt<<<(H1024 * H512 + 255) / 256, 256>>>(c6_w, C6_OFF, H512, H512, H1024);
    k_wt<<<(H1024 * H1024 + 255) / 256, 256>>>(c7_w, C7_OFF, H1024, H1024, H1024);
    k_wt<<<(H1024 * H1024 + 255) / 256, 256>>>(c8_w, C8_OFF, H1024, H1024, H1024);
    k_wt<<<(FC * H1024 + 255) / 256, 256>>>(fc1_w, FC1_OFF, H1024, H1024, FC);
    k_edge_mlp_deg<<<(EE + 255) / 256, 256>>>(edge_attr, ep_w1, ep_b1, ep_w2, ep_b2, ei);
    k_dis<<<NB_SCAN, 256>>>();
    k_scan_block<<<NB_SCAN, 256>>>();
    k_scan_tops<<<1, 32>>>();
    k_scan_add<<<NB_SCAN, 256>>>();
    k_fill<<<(EE + 255) / 256, 256>>>(ei);

    // embedding MLP (padded x in bufA)
    fastgemm(BUF_A, W1_OFF, emb_b1, BUF_C, NN, H512, 64, 1);      // -> bufC
    fastgemm(BUF_C, W2_OFF, emb_b2, BUF_B, NN, H512, H512, 1);    // h -> bufB

    // conv1: aggregate (512) then transform
    k_gather<<<NN, H512 / 4>>>(BUF_B, BUF_C, H512 / 4);           // agg(h) -> bufC
    fastgemm(BUF_C, C6_OFF, c6_b, BUF_A, NN, H1024, H512, 1);     // h1 -> bufA

    // conv2
    k_gather<<<NN, H1024 / 4>>>(BUF_A, BUF_C, H1024 / 4);
    fastgemm(BUF_C, C7_OFF, c7_b, BUF_B, NN, H1024, H1024, 1);    // h2 -> bufB

    // conv3
    k_gather<<<NN, H1024 / 4>>>(BUF_B, BUF_A, H1024 / 4);
    fastgemm(BUF_A, C8_OFF, c8_b, BUF_C, NN, H1024, H1024, 1);    // h3 -> bufC

    // mean pool
    dim3 pgrid(GG, H1024 / 256);
    k_pool2<<<pgrid, 256>>>(BUF_C, batch);

    // head
    fastgemm(BUF_POOLED, FC1_OFF, fc1_b, BUF_Z, GG, FC, H1024, 1); // z
    k_head<<<GG, 384>>>(head_w, head_b, out);
}

// round 13
// speedup vs baseline: 1.7844x; 1.0613x over previous
#include <cuda_runtime.h>
#include <cuda_fp16.h>
#include <cstdint>

#define NN    50000
#define EE    200000
#define GG    128
#define FIN   40
#define H512  512
#define H1024 1024
#define FC    2048
#define NCLS  345
#define NB_SCAN ((NN + 255) / 256)

// fp16 transposed weight scratch offsets (halves); layout [N][Kpad]
#define W1_OFF   0
#define W2_OFF   32768
#define C6_OFF   294912
#define C7_OFF   819200
#define C8_OFF   1867776
#define FC1_OFF  2916352
#define WH_TOTAL 5013504

// dynamic smem: As[2][128][40] + Bs[2][256][40] halves
#define AS_HALFS (2 * 128 * 40)
#define BS_HALFS (2 * 256 * 40)
#define FG_SMEM ((AS_HALFS + BS_HALFS) * 2)

// ---------------- scratch (static device globals; no allocations) ----------
__device__ __half g_bufA[(size_t)NN * H1024];
__device__ __half g_bufB[(size_t)NN * H1024];
__device__ __half g_bufC[(size_t)NN * H1024];
__device__ __half g_wh[WH_TOTAL];
__device__ __half g_pooled[GG * H1024];
__device__ __half g_z[GG * FC];
__device__ float g_ew[EE];
__device__ float g_deg[NN];
__device__ float g_dis[NN];
__device__ int   g_is64;

// CSR (by destination)
__device__ int   g_ecnt[NN];
__device__ int   g_rowstart[NN];
__device__ int   g_next[NN];
__device__ int   g_csr_src[EE];
__device__ float g_csr_w[EE];
__device__ int   g_blksum[NB_SCAN];

#define BUF_A      0
#define BUF_B      1
#define BUF_C      2
#define BUF_POOLED 3
#define BUF_Z      4
__device__ __forceinline__ __half* sel(int id) {
    switch (id) {
        case BUF_A:      return g_bufA;
        case BUF_B:      return g_bufB;
        case BUF_C:      return g_bufC;
        case BUF_POOLED: return g_pooled;
        case BUF_Z:      return g_z;
    }
    return nullptr;
}

__device__ __forceinline__ int ld_idx(const void* p, long long i) {
    return g_is64 ? (int)((const long long*)p)[i] : ((const int*)p)[i];
}

#define CP_ASYNC16(dst_u32, src_ptr) \
    asm volatile("cp.async.ca.shared.global [%0], [%1], 16;\n" :: "r"(dst_u32), "l"(src_ptr))
#define CP_COMMIT() asm volatile("cp.async.commit_group;\n" ::: "memory")
#define CP_WAIT0()  asm volatile("cp.async.wait_group 0;\n" ::: "memory")

#define LDSM_X4(r0, r1, r2, r3, a) \
    asm volatile("ldmatrix.sync.aligned.m8n8.x4.shared.b16 {%0,%1,%2,%3}, [%4];" \
                 : "=r"(r0), "=r"(r1), "=r"(r2), "=r"(r3) : "r"(a))

// ---------------- dtype detection ------------------------------------------
__global__ void k_detect(const unsigned int* __restrict__ ei_words) {
    __shared__ int found;
    if (threadIdx.x == 0) found = 0;
    __syncthreads();
    for (int i = 1 + 2 * threadIdx.x; i < 4096; i += 2 * blockDim.x)
        if (ei_words[i] != 0u) found = 1;
    __syncthreads();
    if (threadIdx.x == 0) g_is64 = (found ? 0 : 1);
}

__global__ void k_init() {
    int i = blockIdx.x * blockDim.x + threadIdx.x;
    if (i < NN) { g_deg[i] = 1.0f; g_ecnt[i] = 0; }
}

// ---------------- merged weight transpose + fp16 convert ---------------------
// All six weights in one pass; g_wh[off + n*Kpad + k] = fp16(src[k*N + n]).
__global__ void k_wt_all(const float* __restrict__ w1, const float* __restrict__ w2,
                         const float* __restrict__ c6, const float* __restrict__ c7,
                         const float* __restrict__ c8, const float* __restrict__ f1) {
    int i = blockIdx.x * 256 + threadIdx.x;
    if (i >= WH_TOTAL) return;
    const float* src; int off, K, Kpad, N;
    if      (i < W2_OFF)  { src = w1; off = W1_OFF;  K = FIN;   Kpad = 64;    N = H512;  }
    else if (i < C6_OFF)  { src = w2; off = W2_OFF;  K = H512;  Kpad = H512;  N = H512;  }
    else if (i < C7_OFF)  { src = c6; off = C6_OFF;  K = H512;  Kpad = H512;  N = H1024; }
    else if (i < C8_OFF)  { src = c7; off = C7_OFF;  K = H1024; Kpad = H1024; N = H1024; }
    else if (i < FC1_OFF) { src = c8; off = C8_OFF;  K = H1024; Kpad = H1024; N = H1024; }
    else                  { src = f1; off = FC1_OFF; K = H1024; Kpad = H1024; N = FC;    }
    int j = i - off;
    int n = j / Kpad, k = j - n * Kpad;
    float v = (k < K) ? src[(size_t)k * N + n] : 0.0f;
    g_wh[i] = __float2half_rn(v);
}

// ---------------- pad x: [NN][40] fp32 -> bufA [NN][64] fp16 ----------------
__global__ void k_padx(const float* __restrict__ x) {
    int i = blockIdx.x * 256 + threadIdx.x;
    if (i >= NN * 64) return;
    int row = i >> 6, c = i & 63;
    float v = (c < FIN) ? x[(size_t)row * FIN + c] : 0.0f;
    g_bufA[i] = __float2half_rn(v);
}

// ---------------- edge MLP + weighted degree + in-edge count (fused) --------
__global__ void k_edge_mlp_deg(const float* __restrict__ ea,
                               const float* __restrict__ w1, const float* __restrict__ b1,
                               const float* __restrict__ w2, const float* __restrict__ b2,
                               const void* __restrict__ ei) {
    int e = blockIdx.x * blockDim.x + threadIdx.x;
    if (e >= EE) return;
    float a0 = ea[e * 3 + 0], a1 = ea[e * 3 + 1], a2 = ea[e * 3 + 2];
    float acc = b2[0];
#pragma unroll 8
    for (int h = 0; h < 64; h++) {
        float v = b1[h] + a0 * w1[h] + a1 * w1[64 + h] + a2 * w1[128 + h];
        acc += fmaxf(v, 0.0f) * w2[h];
    }
    float ew = 1.0f / (1.0f + expf(-acc));
    g_ew[e] = ew;
    int d = ld_idx(ei, (long long)EE + e);
    if (d >= 0 && d < NN) {
        atomicAdd(&g_deg[d], ew);
        atomicAdd(&g_ecnt[d], 1);
    }
}

__global__ void k_dis() {
    int i = blockIdx.x * blockDim.x + threadIdx.x;
    if (i >= NN) return;
    g_dis[i] = rsqrtf(g_deg[i]);
}

// ---------------- CSR build --------------------------------------------------
__global__ void k_scan_block() {
    __shared__ int s[256];
    int tid = threadIdx.x;
    int i = blockIdx.x * 256 + tid;
    int v = (i < NN) ? g_ecnt[i] : 0;
    s[tid] = v;
    __syncthreads();
#pragma unroll
    for (int off = 1; off < 256; off <<= 1) {
        int t = (tid >= off) ? s[tid - off] : 0;
        __syncthreads();
        s[tid] += t;
        __syncthreads();
    }
    if (i < NN) g_rowstart[i] = s[tid] - v;
    if (tid == 255) g_blksum[blockIdx.x] = s[tid];
}

// parallel scan over NB_SCAN (<=256) block sums, exclusive
__global__ void k_scan_tops() {
    __shared__ int s[256];
    int tid = threadIdx.x;
    int v = (tid < NB_SCAN) ? g_blksum[tid] : 0;
    s[tid] = v;
    __syncthreads();
#pragma unroll
    for (int off = 1; off < 256; off <<= 1) {
        int t = (tid >= off) ? s[tid - off] : 0;
        __syncthreads();
        s[tid] += t;
        __syncthreads();
    }
    if (tid < NB_SCAN) g_blksum[tid] = s[tid] - v;
}

__global__ void k_scan_add() {
    int i = blockIdx.x * 256 + threadIdx.x;
    if (i >= NN) return;
    int r = g_rowstart[i] + g_blksum[blockIdx.x];
    g_rowstart[i] = r;
    g_next[i] = r;
}

__global__ void k_fill(const void* __restrict__ ei) {
    int e = blockIdx.x * blockDim.x + threadIdx.x;
    if (e >= EE) return;
    int s = ld_idx(ei, e);
    int d = ld_idx(ei, (long long)EE + e);
    if (s < 0 || s >= NN || d < 0 || d >= NN) return;
    int pos = atomicAdd(&g_next[d], 1);
    g_csr_src[pos] = s;
    g_csr_w[pos]   = g_dis[s] * g_ew[e] * g_dis[d];
}

// ---------------- FAST fp16 GEMM: cp.async + ldmatrix, CTA 128x256 ----------
// 8 warps, warp 64x64, BK=32, mma.m16n8k16.f16 fp32 accum. K%32==0, N%256==0.
__global__ __launch_bounds__(256) void k_fastgemm(
    int aId, int bOff, const float* __restrict__ bias, int cId,
    int M, int N, int K, int doRelu)
{
    extern __shared__ __half smemH[];
    __half* AsBase = smemH;                 // [2][128][40]
    __half* BsBase = smemH + AS_HALFS;      // [2][256][40]

    const __half* __restrict__ A = sel(aId);
    const __half* __restrict__ B = g_wh + bOff;
    __half* __restrict__ C       = sel(cId);

    const int tid  = threadIdx.x;
    const int wid  = tid >> 5;
    const int lane = tid & 31;
    const int grp  = lane >> 2;
    const int tg   = lane & 3;
    const int warp_m = wid & 1;    // 2 warps along M (64 rows)
    const int warp_n = wid >> 1;   // 4 warps along N (64 cols)

    const int blockRow = blockIdx.y * 128;
    const int blockCol = blockIdx.x * 256;

    float acc[4][8][4];
#pragma unroll
    for (int mi = 0; mi < 4; mi++)
#pragma unroll
        for (int ni = 0; ni < 8; ni++)
#pragma unroll
            for (int r = 0; r < 4; r++) acc[mi][ni][r] = 0.0f;

    const int T = K >> 5;

    uint32_t asU = (uint32_t)__cvta_generic_to_shared(AsBase);
    uint32_t bsU = (uint32_t)__cvta_generic_to_shared(BsBase);

    // ldmatrix lane offsets (in halves)
    //   A x4: matrices (rows0-7,k0)(rows8-15,k0)(rows0-7,k8)(rows8-15,k8)
    const int aLaneOff = (lane & 15) * 40 + (lane >> 4) * 8;
    //   B x4: (n0-7,k0)(n0-7,k8)(n8-15,k0)(n8-15,k8) -> {b0,b1}x{ni,ni+1}
    const int bLaneOff = ((lane & 7) + (lane >> 4) * 8) * 40 + ((lane >> 3) & 1) * 8;

    auto load_tile = [&](int it, int buf) {
        const int k0 = it << 5;
        uint32_t aB = asU + buf * (128 * 40 * 2);
        uint32_t bB = bsU + buf * (256 * 40 * 2);
#pragma unroll
        for (int i = 0; i < 2; i++) {
            int q = tid + i * 256;
            int row = q >> 2, c = q & 3;
            int gr = min(blockRow + row, M - 1);
            CP_ASYNC16(aB + row * 80 + c * 16, A + (size_t)gr * K + k0 + c * 8);
        }
#pragma unroll
        for (int i = 0; i < 4; i++) {
            int q = tid + i * 256;
            int row = q >> 2, c = q & 3;
            CP_ASYNC16(bB + row * 80 + c * 16, B + (size_t)(blockCol + row) * K + k0 + c * 8);
        }
        CP_COMMIT();
    };

    load_tile(0, 0);

    for (int it = 0; it < T; it++) {
        const int buf = it & 1;
        CP_WAIT0();
        __syncthreads();
        if (it + 1 < T) load_tile(it + 1, buf ^ 1);

        uint32_t aB = asU + buf * (128 * 40 * 2);
        uint32_t bB = bsU + buf * (256 * 40 * 2);
#pragma unroll
        for (int ks = 0; ks < 2; ks++) {
            const int kb = ks * 16;
            uint32_t af[4][4], bf[8][2];
#pragma unroll
            for (int mi = 0; mi < 4; mi++) {
                int rb = warp_m * 64 + mi * 16;
                uint32_t addr = aB + (rb * 40 + kb + aLaneOff) * 2;
                LDSM_X4(af[mi][0], af[mi][1], af[mi][2], af[mi][3], addr);
            }
#pragma unroll
            for (int nj = 0; nj < 4; nj++) {
                int nb = warp_n * 64 + nj * 16;
                uint32_t addr = bB + (nb * 40 + kb + bLaneOff) * 2;
                LDSM_X4(bf[2 * nj][0], bf[2 * nj][1], bf[2 * nj + 1][0], bf[2 * nj + 1][1], addr);
            }
#pragma unroll
            for (int mi = 0; mi < 4; mi++)
#pragma unroll
                for (int ni = 0; ni < 8; ni++) {
                    asm volatile(
                        "mma.sync.aligned.m16n8k16.row.col.f32.f16.f16.f32 "
                        "{%0,%1,%2,%3}, {%4,%5,%6,%7}, {%8,%9}, {%0,%1,%2,%3};\n"
                        : "+f"(acc[mi][ni][0]), "+f"(acc[mi][ni][1]),
                          "+f"(acc[mi][ni][2]), "+f"(acc[mi][ni][3])
                        : "r"(af[mi][0]), "r"(af[mi][1]), "r"(af[mi][2]), "r"(af[mi][3]),
                          "r"(bf[ni][0]), "r"(bf[ni][1]));
                }
        }
    }

#pragma unroll
    for (int mi = 0; mi < 4; mi++) {
        int r0 = blockRow + warp_m * 64 + mi * 16 + grp;
        int r1 = r0 + 8;
#pragma unroll
        for (int ni = 0; ni < 8; ni++) {
            int c0 = blockCol + warp_n * 64 + ni * 8 + 2 * tg;
            float b0 = bias[c0], b1 = bias[c0 + 1];
            if (r0 < M) {
                float v0 = acc[mi][ni][0] + b0;
                float v1 = acc[mi][ni][1] + b1;
                if (doRelu) { v0 = fmaxf(v0, 0.0f); v1 = fmaxf(v1, 0.0f); }
                *(__half2*)(C + (size_t)r0 * N + c0) = __floats2half2_rn(v0, v1);
            }
            if (r1 < M) {
                float v0 = acc[mi][ni][2] + b0;
                float v1 = acc[mi][ni][3] + b1;
                if (doRelu) { v0 = fmaxf(v0, 0.0f); v1 = fmaxf(v1, 0.0f); }
                *(__half2*)(C + (size_t)r1 * N + c0) = __floats2half2_rn(v0, v1);
            }
        }
    }
}

// ---------------- gather: out[n,:] = h2(dis^2 t[n,:] + sum w t[src,:]) -------
__global__ void k_gather(int tId, int outId, int Fq) {
    const uint2* __restrict__ t2 = (const uint2*)sel(tId);
    uint2* __restrict__ o2       = (uint2*)sel(outId);

    int node = blockIdx.x;
    int tid  = threadIdx.x;

    float d = g_dis[node];
    float sw = d * d;
    uint2 u = t2[(size_t)node * Fq + tid];
    const __half2* uh = (const __half2*)&u;
    float2 p0 = __half22float2(uh[0]);
    float2 p1 = __half22float2(uh[1]);
    float a0 = sw * p0.x, a1 = sw * p0.y, a2 = sw * p1.x, a3 = sw * p1.y;

    int s = g_rowstart[node];
    int e = s + g_ecnt[node];
    for (int i = s; i < e; i++) {
        int src = g_csr_src[i];
        float w = g_csr_w[i];
        uint2 v = t2[(size_t)src * Fq + tid];
        const __half2* vh = (const __half2*)&v;
        float2 q0 = __half22float2(vh[0]);
        float2 q1 = __half22float2(vh[1]);
        a0 += w * q0.x; a1 += w * q0.y; a2 += w * q1.x; a3 += w * q1.y;
    }
    uint2 o;
    ((__half2*)&o)[0] = __floats2half2_rn(a0, a1);
    ((__half2*)&o)[1] = __floats2half2_rn(a2, a3);
    o2[(size_t)node * Fq + tid] = o;
}

// ---------------- segmented mean pooling (batch sorted) ----------------------
__global__ void k_pool2(int hId, const void* __restrict__ batch) {
    const __half* __restrict__ h = sel(hId);
    int g = blockIdx.x;
    int f = blockIdx.y * 256 + threadIdx.x;

    int lo = 0, hi = NN;
    while (lo < hi) { int mid = (lo + hi) >> 1; if (ld_idx(batch, mid) < g) lo = mid + 1; else hi = mid; }
    int start = lo;
    lo = start; hi = NN;
    while (lo < hi) { int mid = (lo + hi) >> 1; if (ld_idx(batch, mid) < g + 1) lo = mid + 1; else hi = mid; }
    int end = lo;

    float acc = 0.0f;
    for (int n = start; n < end; n++)
        acc += __half2float(h[(size_t)n * H1024 + f]);
    float cnt = (float)(end - start);
    g_pooled[g * H1024 + f] = __float2half_rn(acc / fmaxf(cnt, 1.0f));
}

// ---------------- head: out[g,j] = head_b[j] + dot(z[g,:], head_w[:,j]) -----
__global__ __launch_bounds__(384) void k_head(const float* __restrict__ hw,
                                              const float* __restrict__ hb,
                                              float* __restrict__ out) {
    __shared__ float zs[FC];
    int g = blockIdx.x;
    for (int k = threadIdx.x; k < FC; k += blockDim.x)
        zs[k] = __half2float(g_z[(size_t)g * FC + k]);
    __syncthreads();
    int j = threadIdx.x;
    if (j >= NCLS) return;
    float acc = hb[j];
#pragma unroll 8
    for (int k = 0; k < FC; k++)
        acc = fmaf(zs[k], hw[(size_t)k * NCLS + j], acc);
    out[(size_t)g * NCLS + j] = acc;
}

// ---------------- host orchestration ---------------------------------------
static void fastgemm(int aId, int bOff, const float* bias, int cId,
                     int M, int N, int K, int relu) {
    dim3 grid(N / 256, (M + 127) / 128);
    k_fastgemm<<<grid, 256, FG_SMEM>>>(aId, bOff, bias, cId, M, N, K, relu);
}

extern "C" void kernel_launch(void* const* d_in, const int* in_sizes, int n_in,
                              void* d_out, int out_size) {
    const float* x         = (const float*)d_in[0];
    const float* edge_attr = (const float*)d_in[1];
    const void*  ei        = d_in[2];
    const void*  batch     = d_in[3];
    const float *emb_w1 = (const float*)d_in[4],  *emb_b1 = (const float*)d_in[5];
    const float *emb_w2 = (const float*)d_in[6],  *emb_b2 = (const float*)d_in[7];
    const float *ep_w1  = (const float*)d_in[8],  *ep_b1  = (const float*)d_in[9];
    const float *ep_w2  = (const float*)d_in[10], *ep_b2  = (const float*)d_in[11];
    const float *c6_w   = (const float*)d_in[12], *c6_b   = (const float*)d_in[13];
    const float *c7_w   = (const float*)d_in[14], *c7_b   = (const float*)d_in[15];
    const float *c8_w   = (const float*)d_in[16], *c8_b   = (const float*)d_in[17];
    const float *fc1_w  = (const float*)d_in[18], *fc1_b  = (const float*)d_in[19];
    const float *head_w = (const float*)d_in[20], *head_b = (const float*)d_in[21];
    float* out = (float*)d_out;

    cudaFuncSetAttribute(k_fastgemm, cudaFuncAttributeMaxDynamicSharedMemorySize, FG_SMEM);

    // preprocessing: dtype, pad x, fp16 weights, edge weights + degree, CSR
    k_detect<<<1, 256>>>((const unsigned int*)ei);
    k_init<<<NB_SCAN, 256>>>();
    k_padx<<<(NN * 64 + 255) / 256, 256>>>(x);
    k_wt_all<<<(WH_TOTAL + 255) / 256, 256>>>(emb_w1, emb_w2, c6_w, c7_w, c8_w, fc1_w);
    k_edge_mlp_deg<<<(EE + 255) / 256, 256>>>(edge_attr, ep_w1, ep_b1, ep_w2, ep_b2, ei);
    k_dis<<<NB_SCAN, 256>>>();
    k_scan_block<<<NB_SCAN, 256>>>();
    k_scan_tops<<<1, 256>>>();
    k_scan_add<<<NB_SCAN, 256>>>();
    k_fill<<<(EE + 255) / 256, 256>>>(ei);

    // embedding MLP (padded x in bufA)
    fastgemm(BUF_A, W1_OFF, emb_b1, BUF_C, NN, H512, 64, 1);      // -> bufC
    fastgemm(BUF_C, W2_OFF, emb_b2, BUF_B, NN, H512, H512, 1);    // h -> bufB

    // conv1: aggregate (512) then transform
    k_gather<<<NN, H512 / 4>>>(BUF_B, BUF_C, H512 / 4);           // agg(h) -> bufC
    fastgemm(BUF_C, C6_OFF, c6_b, BUF_A, NN, H1024, H512, 1);     // h1 -> bufA

    // conv2
    k_gather<<<NN, H1024 / 4>>>(BUF_A, BUF_C, H1024 / 4);
    fastgemm(BUF_C, C7_OFF, c7_b, BUF_B, NN, H1024, H1024, 1);    // h2 -> bufB

    // conv3
    k_gather<<<NN, H1024 / 4>>>(BUF_B, BUF_A, H1024 / 4);
    fastgemm(BUF_A, C8_OFF, c8_b, BUF_C, NN, H1024, H1024, 1);    // h3 -> bufC

    // mean pool
    dim3 pgrid(GG, H1024 / 256);
    k_pool2<<<pgrid, 256>>>(BUF_C, batch);

    // head
    fastgemm(BUF_POOLED, FC1_OFF, fc1_b, BUF_Z, GG, FC, H1024, 1); // z
    k_head<<<GG, 384>>>(head_w, head_b, out);
}

// round 14
// speedup vs baseline: 1.9321x; 1.0828x over previous
#include <cuda_runtime.h>
#include <cuda_fp16.h>
#include <cstdint>

#define NN    50000
#define EE    200000
#define GG    128
#define FIN   40
#define H512  512
#define H1024 1024
#define FC    2048
#define NCLS  345
#define NB_SCAN ((NN + 255) / 256)

// fp16 transposed weight scratch offsets (halves); layout [N][Kpad]
#define W1_OFF   0
#define W2_OFF   32768
#define C6_OFF   294912
#define C7_OFF   819200
#define C8_OFF   1867776
#define FC1_OFF  2916352
#define WH_TOTAL 5013504

// dynamic smem: As[3][128][40] + Bs[3][256][40] halves (3-stage pipeline)
#define AS_BUF   (128 * 40)
#define BS_BUF   (256 * 40)
#define AS_HALFS (3 * AS_BUF)
#define BS_HALFS (3 * BS_BUF)
#define FG_SMEM ((AS_HALFS + BS_HALFS) * 2)

// ---------------- scratch (static device globals; no allocations) ----------
__device__ __half g_bufA[(size_t)NN * H1024];
__device__ __half g_bufB[(size_t)NN * H1024];
__device__ __half g_bufC[(size_t)NN * H1024];
__device__ __half g_wh[WH_TOTAL];
__device__ __half g_pooled[GG * H1024];
__device__ __half g_z[GG * FC];
__device__ float g_ew[EE];
__device__ float g_deg[NN];
__device__ float g_dis[NN];
__device__ int   g_is64;

// CSR (by destination)
__device__ int   g_ecnt[NN];
__device__ int   g_rowstart[NN];
__device__ int   g_next[NN];
__device__ int   g_csr_src[EE];
__device__ float g_csr_w[EE];
__device__ int   g_blksum[NB_SCAN];

#define BUF_A      0
#define BUF_B      1
#define BUF_C      2
#define BUF_POOLED 3
#define BUF_Z      4
__device__ __forceinline__ __half* sel(int id) {
    switch (id) {
        case BUF_A:      return g_bufA;
        case BUF_B:      return g_bufB;
        case BUF_C:      return g_bufC;
        case BUF_POOLED: return g_pooled;
        case BUF_Z:      return g_z;
    }
    return nullptr;
}

__device__ __forceinline__ int ld_idx(const void* p, long long i) {
    return g_is64 ? (int)((const long long*)p)[i] : ((const int*)p)[i];
}

#define CP_ASYNC16(dst_u32, src_ptr) \
    asm volatile("cp.async.ca.shared.global [%0], [%1], 16;\n" :: "r"(dst_u32), "l"(src_ptr))
#define CP_COMMIT() asm volatile("cp.async.commit_group;\n" ::: "memory")
#define CP_WAIT0()  asm volatile("cp.async.wait_group 0;\n" ::: "memory")
#define CP_WAIT1()  asm volatile("cp.async.wait_group 1;\n" ::: "memory")

#define LDSM_X4(r0, r1, r2, r3, a) \
    asm volatile("ldmatrix.sync.aligned.m8n8.x4.shared.b16 {%0,%1,%2,%3}, [%4];" \
                 : "=r"(r0), "=r"(r1), "=r"(r2), "=r"(r3) : "r"(a))

// ---------------- dtype detection ------------------------------------------
__global__ void k_detect(const unsigned int* __restrict__ ei_words) {
    __shared__ int found;
    if (threadIdx.x == 0) found = 0;
    __syncthreads();
    for (int i = 1 + 2 * threadIdx.x; i < 4096; i += 2 * blockDim.x)
        if (ei_words[i] != 0u) found = 1;
    __syncthreads();
    if (threadIdx.x == 0) g_is64 = (found ? 0 : 1);
}

__global__ void k_init() {
    int i = blockIdx.x * blockDim.x + threadIdx.x;
    if (i < NN) { g_deg[i] = 1.0f; g_ecnt[i] = 0; }
}

// ---------------- coalesced weight transpose + fp16 convert ------------------
// dst[n*Kpad + k] = fp16(src[k*N + n]); 32x32 tiled; zero pad K..Kpad.
__global__ void k_wtT(const float* __restrict__ src, int off, int K, int Kpad, int N) {
    __shared__ float t[32][33];
    int k0 = blockIdx.x * 32;
    int n0 = blockIdx.y * 32;
    int tx = threadIdx.x, ty = threadIdx.y;    // 32 x 8
#pragma unroll
    for (int i = 0; i < 4; i++) {
        int k = k0 + ty + i * 8;
        int n = n0 + tx;
        t[ty + i * 8][tx] = (k < K) ? src[(size_t)k * N + n] : 0.0f;
    }
    __syncthreads();
#pragma unroll
    for (int i = 0; i < 4; i++) {
        int n = n0 + ty + i * 8;
        int k = k0 + tx;
        g_wh[off + (size_t)n * Kpad + k] = __float2half_rn(t[tx][ty + i * 8]);
    }
}

// ---------------- pad x: [NN][40] fp32 -> bufA [NN][64] fp16 ----------------
__global__ void k_padx(const float* __restrict__ x) {
    int i = blockIdx.x * 256 + threadIdx.x;
    if (i >= NN * 64) return;
    int row = i >> 6, c = i & 63;
    float v = (c < FIN) ? x[(size_t)row * FIN + c] : 0.0f;
    g_bufA[i] = __float2half_rn(v);
}

// ---------------- edge MLP + weighted degree + in-edge count (fused) --------
__global__ void k_edge_mlp_deg(const float* __restrict__ ea,
                               const float* __restrict__ w1, const float* __restrict__ b1,
                               const float* __restrict__ w2, const float* __restrict__ b2,
                               const void* __restrict__ ei) {
    int e = blockIdx.x * blockDim.x + threadIdx.x;
    if (e >= EE) return;
    float a0 = ea[e * 3 + 0], a1 = ea[e * 3 + 1], a2 = ea[e * 3 + 2];
    float acc = b2[0];
#pragma unroll 8
    for (int h = 0; h < 64; h++) {
        float v = b1[h] + a0 * w1[h] + a1 * w1[64 + h] + a2 * w1[128 + h];
        acc += fmaxf(v, 0.0f) * w2[h];
    }
    float ew = 1.0f / (1.0f + expf(-acc));
    g_ew[e] = ew;
    int d = ld_idx(ei, (long long)EE + e);
    if (d >= 0 && d < NN) {
        atomicAdd(&g_deg[d], ew);
        atomicAdd(&g_ecnt[d], 1);
    }
}

// ---------------- CSR build (k_dis fused into scan_block) --------------------
__global__ void k_scan_block() {
    __shared__ int s[256];
    int tid = threadIdx.x;
    int i = blockIdx.x * 256 + tid;
    if (i < NN) g_dis[i] = rsqrtf(g_deg[i]);   // fused dis
    int v = (i < NN) ? g_ecnt[i] : 0;
    s[tid] = v;
    __syncthreads();
#pragma unroll
    for (int off = 1; off < 256; off <<= 1) {
        int t = (tid >= off) ? s[tid - off] : 0;
        __syncthreads();
        s[tid] += t;
        __syncthreads();
    }
    if (i < NN) g_rowstart[i] = s[tid] - v;
    if (tid == 255) g_blksum[blockIdx.x] = s[tid];
}

// parallel scan over NB_SCAN (<=256) block sums, exclusive
__global__ void k_scan_tops() {
    __shared__ int s[256];
    int tid = threadIdx.x;
    int v = (tid < NB_SCAN) ? g_blksum[tid] : 0;
    s[tid] = v;
    __syncthreads();
#pragma unroll
    for (int off = 1; off < 256; off <<= 1) {
        int t = (tid >= off) ? s[tid - off] : 0;
        __syncthreads();
        s[tid] += t;
        __syncthreads();
    }
    if (tid < NB_SCAN) g_blksum[tid] = s[tid] - v;
}

__global__ void k_scan_add() {
    int i = blockIdx.x * 256 + threadIdx.x;
    if (i >= NN) return;
    int r = g_rowstart[i] + g_blksum[blockIdx.x];
    g_rowstart[i] = r;
    g_next[i] = r;
}

__global__ void k_fill(const void* __restrict__ ei) {
    int e = blockIdx.x * blockDim.x + threadIdx.x;
    if (e >= EE) return;
    int s = ld_idx(ei, e);
    int d = ld_idx(ei, (long long)EE + e);
    if (s < 0 || s >= NN || d < 0 || d >= NN) return;
    int pos = atomicAdd(&g_next[d], 1);
    g_csr_src[pos] = s;
    g_csr_w[pos]   = g_dis[s] * g_ew[e] * g_dis[d];
}

// ---------------- FAST fp16 GEMM: 3-stage cp.async + ldmatrix ----------------
// CTA 128x256, 8 warps 64x64, BK=32, mma.m16n8k16 fp32 accum. K%32==0, N%256==0.
__global__ __launch_bounds__(256) void k_fastgemm(
    int aId, int bOff, const float* __restrict__ bias, int cId,
    int M, int N, int K, int doRelu)
{
    extern __shared__ __half smemH[];
    const __half* __restrict__ A = sel(aId);
    const __half* __restrict__ B = g_wh + bOff;
    __half* __restrict__ C       = sel(cId);

    const int tid  = threadIdx.x;
    const int wid  = tid >> 5;
    const int lane = tid & 31;
    const int grp  = lane >> 2;
    const int tg   = lane & 3;
    const int warp_m = wid & 1;    // 2 warps along M (64 rows)
    const int warp_n = wid >> 1;   // 4 warps along N (64 cols)

    const int blockRow = blockIdx.y * 128;
    const int blockCol = blockIdx.x * 256;

    float acc[4][8][4];
#pragma unroll
    for (int mi = 0; mi < 4; mi++)
#pragma unroll
        for (int ni = 0; ni < 8; ni++)
#pragma unroll
            for (int r = 0; r < 4; r++) acc[mi][ni][r] = 0.0f;

    const int T = K >> 5;

    uint32_t asU = (uint32_t)__cvta_generic_to_shared(smemH);
    uint32_t bsU = asU + AS_HALFS * 2;

    const int aLaneOff = (lane & 15) * 40 + (lane >> 4) * 8;
    const int bLaneOff = ((lane & 7) + (lane >> 4) * 8) * 40 + ((lane >> 3) & 1) * 8;

    auto load_tile = [&](int it, int buf) {
        const int k0 = it << 5;
        uint32_t aB = asU + buf * (AS_BUF * 2);
        uint32_t bB = bsU + buf * (BS_BUF * 2);
#pragma unroll
        for (int i = 0; i < 2; i++) {
            int q = tid + i * 256;
            int row = q >> 2, c = q & 3;
            int gr = min(blockRow + row, M - 1);
            CP_ASYNC16(aB + row * 80 + c * 16, A + (size_t)gr * K + k0 + c * 8);
        }
#pragma unroll
        for (int i = 0; i < 4; i++) {
            int q = tid + i * 256;
            int row = q >> 2, c = q & 3;
            CP_ASYNC16(bB + row * 80 + c * 16, B + (size_t)(blockCol + row) * K + k0 + c * 8);
        }
        CP_COMMIT();
    };

    load_tile(0, 0);
    load_tile(1, 1);   // T >= 2 for all uses (K >= 64)

    for (int it = 0; it < T; it++) {
        const int buf = it % 3;
        if (it + 1 < T) CP_WAIT1(); else CP_WAIT0();
        __syncthreads();
        if (it + 2 < T) load_tile(it + 2, (it + 2) % 3);

        uint32_t aB = asU + buf * (AS_BUF * 2);
        uint32_t bB = bsU + buf * (BS_BUF * 2);
#pragma unroll
        for (int ks = 0; ks < 2; ks++) {
            const int kb = ks * 16;
            uint32_t af[4][4], bf[8][2];
#pragma unroll
            for (int mi = 0; mi < 4; mi++) {
                int rb = warp_m * 64 + mi * 16;
                uint32_t addr = aB + (rb * 40 + kb + aLaneOff) * 2;
                LDSM_X4(af[mi][0], af[mi][1], af[mi][2], af[mi][3], addr);
            }
#pragma unroll
            for (int nj = 0; nj < 4; nj++) {
                int nb = warp_n * 64 + nj * 16;
                uint32_t addr = bB + (nb * 40 + kb + bLaneOff) * 2;
                LDSM_X4(bf[2 * nj][0], bf[2 * nj][1], bf[2 * nj + 1][0], bf[2 * nj + 1][1], addr);
            }
#pragma unroll
            for (int mi = 0; mi < 4; mi++)
#pragma unroll
                for (int ni = 0; ni < 8; ni++) {
                    asm volatile(
                        "mma.sync.aligned.m16n8k16.row.col.f32.f16.f16.f32 "
                        "{%0,%1,%2,%3}, {%4,%5,%6,%7}, {%8,%9}, {%0,%1,%2,%3};\n"
                        : "+f"(acc[mi][ni][0]), "+f"(acc[mi][ni][1]),
                          "+f"(acc[mi][ni][2]), "+f"(acc[mi][ni][3])
                        : "r"(af[mi][0]), "r"(af[mi][1]), "r"(af[mi][2]), "r"(af[mi][3]),
                          "r"(bf[ni][0]), "r"(bf[ni][1]));
                }
        }
    }

#pragma unroll
    for (int mi = 0; mi < 4; mi++) {
        int r0 = blockRow + warp_m * 64 + mi * 16 + grp;
        int r1 = r0 + 8;
#pragma unroll
        for (int ni = 0; ni < 8; ni++) {
            int c0 = blockCol + warp_n * 64 + ni * 8 + 2 * tg;
            float b0 = bias[c0], b1 = bias[c0 + 1];
            if (r0 < M) {
                float v0 = acc[mi][ni][0] + b0;
                float v1 = acc[mi][ni][1] + b1;
                if (doRelu) { v0 = fmaxf(v0, 0.0f); v1 = fmaxf(v1, 0.0f); }
                *(__half2*)(C + (size_t)r0 * N + c0) = __floats2half2_rn(v0, v1);
            }
            if (r1 < M) {
                float v0 = acc[mi][ni][2] + b0;
                float v1 = acc[mi][ni][3] + b1;
                if (doRelu) { v0 = fmaxf(v0, 0.0f); v1 = fmaxf(v1, 0.0f); }
                *(__half2*)(C + (size_t)r1 * N + c0) = __floats2half2_rn(v0, v1);
            }
        }
    }
}

// ---------------- gather: out[n,:] = h2(dis^2 t[n,:] + sum w t[src,:]) -------
// blockDim = F/8; each thread handles 8 halves (uint4).
__global__ void k_gather(int tId, int outId, int Fo) {
    const uint4* __restrict__ t4 = (const uint4*)sel(tId);
    uint4* __restrict__ o4       = (uint4*)sel(outId);

    int node = blockIdx.x;
    int tid  = threadIdx.x;

    float d = g_dis[node];
    float sw = d * d;
    uint4 u = t4[(size_t)node * Fo + tid];
    const __half2* uh = (const __half2*)&u;
    float a[8];
#pragma unroll
    for (int j = 0; j < 4; j++) {
        float2 p = __half22float2(uh[j]);
        a[2 * j] = sw * p.x; a[2 * j + 1] = sw * p.y;
    }

    int s = g_rowstart[node];
    int e = s + g_ecnt[node];
    for (int i = s; i < e; i++) {
        int src = g_csr_src[i];
        float w = g_csr_w[i];
        uint4 v = t4[(size_t)src * Fo + tid];
        const __half2* vh = (const __half2*)&v;
#pragma unroll
        for (int j = 0; j < 4; j++) {
            float2 q = __half22float2(vh[j]);
            a[2 * j] += w * q.x; a[2 * j + 1] += w * q.y;
        }
    }
    uint4 o;
    __half2* oh = (__half2*)&o;
#pragma unroll
    for (int j = 0; j < 4; j++)
        oh[j] = __floats2half2_rn(a[2 * j], a[2 * j + 1]);
    o4[(size_t)node * Fo + tid] = o;
}

// ---------------- segmented mean pooling (batch sorted) ----------------------
__global__ void k_pool2(int hId, const void* __restrict__ batch) {
    const __half* __restrict__ h = sel(hId);
    int g = blockIdx.x;
    int f = blockIdx.y * 256 + threadIdx.x;

    int lo = 0, hi = NN;
    while (lo < hi) { int mid = (lo + hi) >> 1; if (ld_idx(batch, mid) < g) lo = mid + 1; else hi = mid; }
    int start = lo;
    lo = start; hi = NN;
    while (lo < hi) { int mid = (lo + hi) >> 1; if (ld_idx(batch, mid) < g + 1) lo = mid + 1; else hi = mid; }
    int end = lo;

    float acc = 0.0f;
    for (int n = start; n < end; n++)
        acc += __half2float(h[(size_t)n * H1024 + f]);
    float cnt = (float)(end - start);
    g_pooled[g * H1024 + f] = __float2half_rn(acc / fmaxf(cnt, 1.0f));
}

// ---------------- head: out[g,j] = head_b[j] + dot(z[g,:], head_w[:,j]) -----
__global__ __launch_bounds__(384) void k_head(const float* __restrict__ hw,
                                              const float* __restrict__ hb,
                                              float* __restrict__ out) {
    __shared__ float zs[FC];
    int g = blockIdx.x;
    for (int k = threadIdx.x; k < FC; k += blockDim.x)
        zs[k] = __half2float(g_z[(size_t)g * FC + k]);
    __syncthreads();
    int j = threadIdx.x;
    if (j >= NCLS) return;
    float acc = hb[j];
#pragma unroll 8
    for (int k = 0; k < FC; k++)
        acc = fmaf(zs[k], hw[(size_t)k * NCLS + j], acc);
    out[(size_t)g * NCLS + j] = acc;
}

// ---------------- host orchestration ---------------------------------------
static void fastgemm(int aId, int bOff, const float* bias, int cId,
                     int M, int N, int K, int relu) {
    dim3 grid(N / 256, (M + 127) / 128);
    k_fastgemm<<<grid, 256, FG_SMEM>>>(aId, bOff, bias, cId, M, N, K, relu);
}
static void wtT(const float* src, int off, int K, int Kpad, int N) {
    dim3 grid(Kpad / 32, N / 32);
    k_wtT<<<grid, dim3(32, 8)>>>(src, off, K, Kpad, N);
}

extern "C" void kernel_launch(void* const* d_in, const int* in_sizes, int n_in,
                              void* d_out, int out_size) {
    const float* x         = (const float*)d_in[0];
    const float* edge_attr = (const float*)d_in[1];
    const void*  ei        = d_in[2];
    const void*  batch     = d_in[3];
    const float *emb_w1 = (const float*)d_in[4],  *emb_b1 = (const float*)d_in[5];
    const float *emb_w2 = (const float*)d_in[6],  *emb_b2 = (const float*)d_in[7];
    const float *ep_w1  = (const float*)d_in[8],  *ep_b1  = (const float*)d_in[9];
    const float *ep_w2  = (const float*)d_in[10], *ep_b2  = (const float*)d_in[11];
    const float *c6_w   = (const float*)d_in[12], *c6_b   = (const float*)d_in[13];
    const float *c7_w   = (const float*)d_in[14], *c7_b   = (const float*)d_in[15];
    const float *c8_w   = (const float*)d_in[16], *c8_b   = (const float*)d_in[17];
    const float *fc1_w  = (const float*)d_in[18], *fc1_b  = (const float*)d_in[19];
    const float *head_w = (const float*)d_in[20], *head_b = (const float*)d_in[21];
    float* out = (float*)d_out;

    cudaFuncSetAttribute(k_fastgemm, cudaFuncAttributeMaxDynamicSharedMemorySize, FG_SMEM);

    // preprocessing: dtype, pad x, fp16 weights (coalesced), edge weights, CSR
    k_detect<<<1, 256>>>((const unsigned int*)ei);
    k_init<<<NB_SCAN, 256>>>();
    k_padx<<<(NN * 64 + 255) / 256, 256>>>(x);
    wtT(emb_w1, W1_OFF, FIN, 64, H512);
    wtT(emb_w2, W2_OFF, H512, H512, H512);
    wtT(c6_w, C6_OFF, H512, H512, H1024);
    wtT(c7_w, C7_OFF, H1024, H1024, H1024);
    wtT(c8_w, C8_OFF, H1024, H1024, H1024);
    wtT(fc1_w, FC1_OFF, H1024, H1024, FC);
    k_edge_mlp_deg<<<(EE + 255) / 256, 256>>>(edge_attr, ep_w1, ep_b1, ep_w2, ep_b2, ei);
    k_scan_block<<<NB_SCAN, 256>>>();   // also computes dis
    k_scan_tops<<<1, 256>>>();
    k_scan_add<<<NB_SCAN, 256>>>();
    k_fill<<<(EE + 255) / 256, 256>>>(ei);

    // embedding MLP (padded x in bufA)
    fastgemm(BUF_A, W1_OFF, emb_b1, BUF_C, NN, H512, 64, 1);      // -> bufC
    fastgemm(BUF_C, W2_OFF, emb_b2, BUF_B, NN, H512, H512, 1);    // h -> bufB

    // conv1: aggregate (512) then transform
    k_gather<<<NN, H512 / 8>>>(BUF_B, BUF_C, H512 / 8);           // agg(h) -> bufC
    fastgemm(BUF_C, C6_OFF, c6_b, BUF_A, NN, H1024, H512, 1);     // h1 -> bufA

    // conv2
    k_gather<<<NN, H1024 / 8>>>(BUF_A, BUF_C, H1024 / 8);
    fastgemm(BUF_C, C7_OFF, c7_b, BUF_B, NN, H1024, H1024, 1);    // h2 -> bufB

    // conv3
    k_gather<<<NN, H1024 / 8>>>(BUF_B, BUF_A, H1024 / 8);
    fastgemm(BUF_A, C8_OFF, c8_b, BUF_C, NN, H1024, H1024, 1);    // h3 -> bufC

    // mean pool
    dim3 pgrid(GG, H1024 / 256);
    k_pool2<<<pgrid, 256>>>(BUF_C, batch);

    // head
    fastgemm(BUF_POOLED, FC1_OFF, fc1_b, BUF_Z, GG, FC, H1024, 1); // z
    k_head<<<GG, 384>>>(head_w, head_b, out);
}

// round 15
// speedup vs baseline: 1.9863x; 1.0280x over previous
#include <cuda_runtime.h>
#include <cuda_fp16.h>
#include <cstdint>

#define NN    50000
#define EE    200000
#define GG    128
#define FIN   40
#define H512  512
#define H1024 1024
#define FC    2048
#define NCLS  345
#define NB_SCAN ((NN + 255) / 256)

// fp16 transposed weight scratch offsets (halves); layout [N][Kpad]
#define W1_OFF   0
#define W2_OFF   32768
#define C6_OFF   294912
#define C7_OFF   819200
#define C8_OFF   1867776
#define FC1_OFF  2916352
#define WH_TOTAL 5013504

// dynamic smem: As[4][128][40] + Bs[4][256][40] halves (4-stage pipeline)
#define AS_BUF   (128 * 40)
#define BS_BUF   (256 * 40)
#define N_STAGE  4
#define AS_HALFS (N_STAGE * AS_BUF)
#define BS_HALFS (N_STAGE * BS_BUF)
#define FG_SMEM ((AS_HALFS + BS_HALFS) * 2)

// ---------------- scratch (static device globals; no allocations) ----------
__device__ __half g_bufA[(size_t)NN * H1024];
__device__ __half g_bufB[(size_t)NN * H1024];
__device__ __half g_bufC[(size_t)NN * H1024];
__device__ __half g_wh[WH_TOTAL];
__device__ __half g_pooled[GG * H1024];
__device__ __half g_z[GG * FC];
__device__ float g_ew[EE];
__device__ float g_deg[NN];
__device__ float g_dis[NN];
__device__ int   g_is64;

// CSR (by destination); interleaved {src, w} per edge
__device__ int   g_ecnt[NN];
__device__ int   g_rowstart[NN];
__device__ int   g_next[NN];
__device__ uint2 g_csr[EE];          // .x = src, .y = bits of float w
__device__ int   g_blksum[NB_SCAN];

#define BUF_A      0
#define BUF_B      1
#define BUF_C      2
#define BUF_POOLED 3
#define BUF_Z      4
__device__ __forceinline__ __half* sel(int id) {
    switch (id) {
        case BUF_A:      return g_bufA;
        case BUF_B:      return g_bufB;
        case BUF_C:      return g_bufC;
        case BUF_POOLED: return g_pooled;
        case BUF_Z:      return g_z;
    }
    return nullptr;
}

__device__ __forceinline__ int ld_idx(const void* p, long long i) {
    return g_is64 ? (int)((const long long*)p)[i] : ((const int*)p)[i];
}

#define CP_ASYNC16(dst_u32, src_ptr) \
    asm volatile("cp.async.ca.shared.global [%0], [%1], 16;\n" :: "r"(dst_u32), "l"(src_ptr))
#define CP_COMMIT() asm volatile("cp.async.commit_group;\n" ::: "memory")
#define CP_WAIT0()  asm volatile("cp.async.wait_group 0;\n" ::: "memory")
#define CP_WAIT1()  asm volatile("cp.async.wait_group 1;\n" ::: "memory")
#define CP_WAIT2()  asm volatile("cp.async.wait_group 2;\n" ::: "memory")

#define LDSM_X4(r0, r1, r2, r3, a) \
    asm volatile("ldmatrix.sync.aligned.m8n8.x4.shared.b16 {%0,%1,%2,%3}, [%4];" \
                 : "=r"(r0), "=r"(r1), "=r"(r2), "=r"(r3) : "r"(a))

// ---------------- dtype detection ------------------------------------------
__global__ void k_detect(const unsigned int* __restrict__ ei_words) {
    __shared__ int found;
    if (threadIdx.x == 0) found = 0;
    __syncthreads();
    for (int i = 1 + 2 * threadIdx.x; i < 4096; i += 2 * blockDim.x)
        if (ei_words[i] != 0u) found = 1;
    __syncthreads();
    if (threadIdx.x == 0) g_is64 = (found ? 0 : 1);
}

__global__ void k_init() {
    int i = blockIdx.x * blockDim.x + threadIdx.x;
    if (i < NN) { g_deg[i] = 1.0f; g_ecnt[i] = 0; }
}

// ---------------- coalesced weight transpose + fp16 convert ------------------
__global__ void k_wtT(const float* __restrict__ src, int off, int K, int Kpad, int N) {
    __shared__ float t[32][33];
    int k0 = blockIdx.x * 32;
    int n0 = blockIdx.y * 32;
    int tx = threadIdx.x, ty = threadIdx.y;    // 32 x 8
#pragma unroll
    for (int i = 0; i < 4; i++) {
        int k = k0 + ty + i * 8;
        int n = n0 + tx;
        t[ty + i * 8][tx] = (k < K) ? src[(size_t)k * N + n] : 0.0f;
    }
    __syncthreads();
#pragma unroll
    for (int i = 0; i < 4; i++) {
        int n = n0 + ty + i * 8;
        int k = k0 + tx;
        g_wh[off + (size_t)n * Kpad + k] = __float2half_rn(t[tx][ty + i * 8]);
    }
}

// ---------------- pad x: [NN][40] fp32 -> bufA [NN][64] fp16 ----------------
__global__ void k_padx(const float* __restrict__ x) {
    int i = blockIdx.x * 256 + threadIdx.x;
    if (i >= NN * 64) return;
    int row = i >> 6, c = i & 63;
    float v = (c < FIN) ? x[(size_t)row * FIN + c] : 0.0f;
    g_bufA[i] = __float2half_rn(v);
}

// ---------------- edge MLP + weighted degree + in-edge count (fused) --------
__global__ void k_edge_mlp_deg(const float* __restrict__ ea,
                               const float* __restrict__ w1, const float* __restrict__ b1,
                               const float* __restrict__ w2, const float* __restrict__ b2,
                               const void* __restrict__ ei) {
    int e = blockIdx.x * blockDim.x + threadIdx.x;
    if (e >= EE) return;
    float a0 = ea[e * 3 + 0], a1 = ea[e * 3 + 1], a2 = ea[e * 3 + 2];
    float acc = b2[0];
#pragma unroll 8
    for (int h = 0; h < 64; h++) {
        float v = b1[h] + a0 * w1[h] + a1 * w1[64 + h] + a2 * w1[128 + h];
        acc += fmaxf(v, 0.0f) * w2[h];
    }
    float ew = 1.0f / (1.0f + expf(-acc));
    g_ew[e] = ew;
    int d = ld_idx(ei, (long long)EE + e);
    if (d >= 0 && d < NN) {
        atomicAdd(&g_deg[d], ew);
        atomicAdd(&g_ecnt[d], 1);
    }
}

// ---------------- CSR build (dis fused into scan_block) ----------------------
__global__ void k_scan_block() {
    __shared__ int s[256];
    int tid = threadIdx.x;
    int i = blockIdx.x * 256 + tid;
    if (i < NN) g_dis[i] = rsqrtf(g_deg[i]);
    int v = (i < NN) ? g_ecnt[i] : 0;
    s[tid] = v;
    __syncthreads();
#pragma unroll
    for (int off = 1; off < 256; off <<= 1) {
        int t = (tid >= off) ? s[tid - off] : 0;
        __syncthreads();
        s[tid] += t;
        __syncthreads();
    }
    if (i < NN) g_rowstart[i] = s[tid] - v;
    if (tid == 255) g_blksum[blockIdx.x] = s[tid];
}

__global__ void k_scan_tops() {
    __shared__ int s[256];
    int tid = threadIdx.x;
    int v = (tid < NB_SCAN) ? g_blksum[tid] : 0;
    s[tid] = v;
    __syncthreads();
#pragma unroll
    for (int off = 1; off < 256; off <<= 1) {
        int t = (tid >= off) ? s[tid - off] : 0;
        __syncthreads();
        s[tid] += t;
        __syncthreads();
    }
    if (tid < NB_SCAN) g_blksum[tid] = s[tid] - v;
}

__global__ void k_scan_add() {
    int i = blockIdx.x * 256 + threadIdx.x;
    if (i >= NN) return;
    int r = g_rowstart[i] + g_blksum[blockIdx.x];
    g_rowstart[i] = r;
    g_next[i] = r;
}

__global__ void k_fill(const void* __restrict__ ei) {
    int e = blockIdx.x * blockDim.x + threadIdx.x;
    if (e >= EE) return;
    int s = ld_idx(ei, e);
    int d = ld_idx(ei, (long long)EE + e);
    if (s < 0 || s >= NN || d < 0 || d >= NN) return;
    int pos = atomicAdd(&g_next[d], 1);
    uint2 rec;
    rec.x = (unsigned)s;
    rec.y = __float_as_uint(g_dis[s] * g_ew[e] * g_dis[d]);
    g_csr[pos] = rec;
}

// ---------------- FAST fp16 GEMM: 4-stage cp.async + ldmatrix ----------------
// CTA 128x256, 8 warps 64x64, BK=32, mma.m16n8k16 fp32 accum. K%32==0, N%256==0.
__global__ __launch_bounds__(256) void k_fastgemm(
    int aId, int bOff, const float* __restrict__ bias, int cId,
    int M, int N, int K, int doRelu)
{
    extern __shared__ __half smemH[];
    const __half* __restrict__ A = sel(aId);
    const __half* __restrict__ B = g_wh + bOff;
    __half* __restrict__ C       = sel(cId);

    const int tid  = threadIdx.x;
    const int wid  = tid >> 5;
    const int lane = tid & 31;
    const int grp  = lane >> 2;
    const int tg   = lane & 3;
    const int warp_m = wid & 1;
    const int warp_n = wid >> 1;

    const int blockRow = blockIdx.y * 128;
    const int blockCol = blockIdx.x * 256;

    float acc[4][8][4];
#pragma unroll
    for (int mi = 0; mi < 4; mi++)
#pragma unroll
        for (int ni = 0; ni < 8; ni++)
#pragma unroll
            for (int r = 0; r < 4; r++) acc[mi][ni][r] = 0.0f;

    const int T = K >> 5;

    uint32_t asU = (uint32_t)__cvta_generic_to_shared(smemH);
    uint32_t bsU = asU + AS_HALFS * 2;

    const int aLaneOff = (lane & 15) * 40 + (lane >> 4) * 8;
    const int bLaneOff = ((lane & 7) + (lane >> 4) * 8) * 40 + ((lane >> 3) & 1) * 8;

    auto load_tile = [&](int it, int buf) {
        const int k0 = it << 5;
        uint32_t aB = asU + buf * (AS_BUF * 2);
        uint32_t bB = bsU + buf * (BS_BUF * 2);
#pragma unroll
        for (int i = 0; i < 2; i++) {
            int q = tid + i * 256;
            int row = q >> 2, c = q & 3;
            int gr = min(blockRow + row, M - 1);
            CP_ASYNC16(aB + row * 80 + c * 16, A + (size_t)gr * K + k0 + c * 8);
        }
#pragma unroll
        for (int i = 0; i < 4; i++) {
            int q = tid + i * 256;
            int row = q >> 2, c = q & 3;
            CP_ASYNC16(bB + row * 80 + c * 16, B + (size_t)(blockCol + row) * K + k0 + c * 8);
        }
        CP_COMMIT();
    };

    load_tile(0, 0);
    if (T > 1) load_tile(1, 1);
    if (T > 2) load_tile(2, 2);

    for (int it = 0; it < T; it++) {
        const int buf = it & 3;
        const int rem = T - 1 - it;
        if (rem >= 2) CP_WAIT2();
        else if (rem == 1) CP_WAIT1();
        else CP_WAIT0();
        __syncthreads();
        if (it + 3 < T) load_tile(it + 3, (it + 3) & 3);

        uint32_t aB = asU + buf * (AS_BUF * 2);
        uint32_t bB = bsU + buf * (BS_BUF * 2);
#pragma unroll
        for (int ks = 0; ks < 2; ks++) {
            const int kb = ks * 16;
            uint32_t af[4][4], bf[8][2];
#pragma unroll
            for (int mi = 0; mi < 4; mi++) {
                int rb = warp_m * 64 + mi * 16;
                uint32_t addr = aB + (rb * 40 + kb + aLaneOff) * 2;
                LDSM_X4(af[mi][0], af[mi][1], af[mi][2], af[mi][3], addr);
            }
#pragma unroll
            for (int nj = 0; nj < 4; nj++) {
                int nb = warp_n * 64 + nj * 16;
                uint32_t addr = bB + (nb * 40 + kb + bLaneOff) * 2;
                LDSM_X4(bf[2 * nj][0], bf[2 * nj][1], bf[2 * nj + 1][0], bf[2 * nj + 1][1], addr);
            }
#pragma unroll
            for (int mi = 0; mi < 4; mi++)
#pragma unroll
                for (int ni = 0; ni < 8; ni++) {
                    asm volatile(
                        "mma.sync.aligned.m16n8k16.row.col.f32.f16.f16.f32 "
                        "{%0,%1,%2,%3}, {%4,%5,%6,%7}, {%8,%9}, {%0,%1,%2,%3};\n"
                        : "+f"(acc[mi][ni][0]), "+f"(acc[mi][ni][1]),
                          "+f"(acc[mi][ni][2]), "+f"(acc[mi][ni][3])
                        : "r"(af[mi][0]), "r"(af[mi][1]), "r"(af[mi][2]), "r"(af[mi][3]),
                          "r"(bf[ni][0]), "r"(bf[ni][1]));
                }
        }
    }

#pragma unroll
    for (int mi = 0; mi < 4; mi++) {
        int r0 = blockRow + warp_m * 64 + mi * 16 + grp;
        int r1 = r0 + 8;
#pragma unroll
        for (int ni = 0; ni < 8; ni++) {
            int c0 = blockCol + warp_n * 64 + ni * 8 + 2 * tg;
            float b0 = bias[c0], b1 = bias[c0 + 1];
            if (r0 < M) {
                float v0 = acc[mi][ni][0] + b0;
                float v1 = acc[mi][ni][1] + b1;
                if (doRelu) { v0 = fmaxf(v0, 0.0f); v1 = fmaxf(v1, 0.0f); }
                *(__half2*)(C + (size_t)r0 * N + c0) = __floats2half2_rn(v0, v1);
            }
            if (r1 < M) {
                float v0 = acc[mi][ni][2] + b0;
                float v1 = acc[mi][ni][3] + b1;
                if (doRelu) { v0 = fmaxf(v0, 0.0f); v1 = fmaxf(v1, 0.0f); }
                *(__half2*)(C + (size_t)r1 * N + c0) = __floats2half2_rn(v0, v1);
            }
        }
    }
}

// ---------------- gather: out[n,:] = h2(dis^2 t[n,:] + sum w t[src,:]) -------
// blockDim = F/8; each thread handles 8 halves (uint4). Edge loop unrolled x2.
__global__ void k_gather(int tId, int outId, int Fo) {
    const uint4* __restrict__ t4 = (const uint4*)sel(tId);
    uint4* __restrict__ o4       = (uint4*)sel(outId);

    int node = blockIdx.x;
    int tid  = threadIdx.x;

    float d = g_dis[node];
    float sw = d * d;
    uint4 u = t4[(size_t)node * Fo + tid];
    const __half2* uh = (const __half2*)&u;
    float a[8];
#pragma unroll
    for (int j = 0; j < 4; j++) {
        float2 p = __half22float2(uh[j]);
        a[2 * j] = sw * p.x; a[2 * j + 1] = sw * p.y;
    }

    int s = g_rowstart[node];
    int e = s + g_ecnt[node];
    int i = s;
    for (; i + 1 < e; i += 2) {
        uint2 r0 = g_csr[i];
        uint2 r1 = g_csr[i + 1];
        float w0 = __uint_as_float(r0.y);
        float w1 = __uint_as_float(r1.y);
        uint4 v0 = t4[(size_t)r0.x * Fo + tid];
        uint4 v1 = t4[(size_t)r1.x * Fo + tid];
        const __half2* vh0 = (const __half2*)&v0;
        const __half2* vh1 = (const __half2*)&v1;
#pragma unroll
        for (int j = 0; j < 4; j++) {
            float2 q0 = __half22float2(vh0[j]);
            float2 q1 = __half22float2(vh1[j]);
            a[2 * j]     += w0 * q0.x + w1 * q1.x;
            a[2 * j + 1] += w0 * q0.y + w1 * q1.y;
        }
    }
    if (i < e) {
        uint2 r0 = g_csr[i];
        float w0 = __uint_as_float(r0.y);
        uint4 v0 = t4[(size_t)r0.x * Fo + tid];
        const __half2* vh0 = (const __half2*)&v0;
#pragma unroll
        for (int j = 0; j < 4; j++) {
            float2 q0 = __half22float2(vh0[j]);
            a[2 * j] += w0 * q0.x; a[2 * j + 1] += w0 * q0.y;
        }
    }
    uint4 o;
    __half2* oh = (__half2*)&o;
#pragma unroll
    for (int j = 0; j < 4; j++)
        oh[j] = __floats2half2_rn(a[2 * j], a[2 * j + 1]);
    o4[(size_t)node * Fo + tid] = o;
}

// ---------------- segmented mean pooling (batch sorted) ----------------------
__global__ void k_pool2(int hId, const void* __restrict__ batch) {
    const __half* __restrict__ h = sel(hId);
    int g = blockIdx.x;
    int f = blockIdx.y * 256 + threadIdx.x;

    int lo = 0, hi = NN;
    while (lo < hi) { int mid = (lo + hi) >> 1; if (ld_idx(batch, mid) < g) lo = mid + 1; else hi = mid; }
    int start = lo;
    lo = start; hi = NN;
    while (lo < hi) { int mid = (lo + hi) >> 1; if (ld_idx(batch, mid) < g + 1) lo = mid + 1; else hi = mid; }
    int end = lo;

    float acc = 0.0f;
    for (int n = start; n < end; n++)
        acc += __half2float(h[(size_t)n * H1024 + f]);
    float cnt = (float)(end - start);
    g_pooled[g * H1024 + f] = __float2half_rn(acc / fmaxf(cnt, 1.0f));
}

// ---------------- head: out[g,j] = head_b[j] + dot(z[g,:], head_w[:,j]) -----
__global__ __launch_bounds__(384) void k_head(const float* __restrict__ hw,
                                              const float* __restrict__ hb,
                                              float* __restrict__ out) {
    __shared__ float zs[FC];
    int g = blockIdx.x;
    for (int k = threadIdx.x; k < FC; k += blockDim.x)
        zs[k] = __half2float(g_z[(size_t)g * FC + k]);
    __syncthreads();
    int j = threadIdx.x;
    if (j >= NCLS) return;
    float acc = hb[j];
#pragma unroll 8
    for (int k = 0; k < FC; k++)
        acc = fmaf(zs[k], hw[(size_t)k * NCLS + j], acc);
    out[(size_t)g * NCLS + j] = acc;
}

// ---------------- host orchestration ---------------------------------------
static void fastgemm(int aId, int bOff, const float* bias, int cId,
                     int M, int N, int K, int relu) {
    dim3 grid(N / 256, (M + 127) / 128);
    k_fastgemm<<<grid, 256, FG_SMEM>>>(aId, bOff, bias, cId, M, N, K, relu);
}
static void wtT(const float* src, int off, int K, int Kpad, int N) {
    dim3 grid(Kpad / 32, N / 32);
    k_wtT<<<grid, dim3(32, 8)>>>(src, off, K, Kpad, N);
}

extern "C" void kernel_launch(void* const* d_in, const int* in_sizes, int n_in,
                              void* d_out, int out_size) {
    const float* x         = (const float*)d_in[0];
    const float* edge_attr = (const float*)d_in[1];
    const void*  ei        = d_in[2];
    const void*  batch     = d_in[3];
    const float *emb_w1 = (const float*)d_in[4],  *emb_b1 = (const float*)d_in[5];
    const float *emb_w2 = (const float*)d_in[6],  *emb_b2 = (const float*)d_in[7];
    const float *ep_w1  = (const float*)d_in[8],  *ep_b1  = (const float*)d_in[9];
    const float *ep_w2  = (const float*)d_in[10], *ep_b2  = (const float*)d_in[11];
    const float *c6_w   = (const float*)d_in[12], *c6_b   = (const float*)d_in[13];
    const float *c7_w   = (const float*)d_in[14], *c7_b   = (const float*)d_in[15];
    const float *c8_w   = (const float*)d_in[16], *c8_b   = (const float*)d_in[17];
    const float *fc1_w  = (const float*)d_in[18], *fc1_b  = (const float*)d_in[19];
    const float *head_w = (const float*)d_in[20], *head_b = (const float*)d_in[21];
    float* out = (float*)d_out;

    cudaFuncSetAttribute(k_fastgemm, cudaFuncAttributeMaxDynamicSharedMemorySize, FG_SMEM);

    // preprocessing
    k_detect<<<1, 256>>>((const unsigned int*)ei);
    k_init<<<NB_SCAN, 256>>>();
    k_padx<<<(NN * 64 + 255) / 256, 256>>>(x);
    wtT(emb_w1, W1_OFF, FIN, 64, H512);
    wtT(emb_w2, W2_OFF, H512, H512, H512);
    wtT(c6_w, C6_OFF, H512, H512, H1024);
    wtT(c7_w, C7_OFF, H1024, H1024, H1024);
    wtT(c8_w, C8_OFF, H1024, H1024, H1024);
    wtT(fc1_w, FC1_OFF, H1024, H1024, FC);
    k_edge_mlp_deg<<<(EE + 255) / 256, 256>>>(edge_attr, ep_w1, ep_b1, ep_w2, ep_b2, ei);
    k_scan_block<<<NB_SCAN, 256>>>();   // also computes dis
    k_scan_tops<<<1, 256>>>();
    k_scan_add<<<NB_SCAN, 256>>>();
    k_fill<<<(EE + 255) / 256, 256>>>(ei);

    // embedding MLP (padded x in bufA)
    fastgemm(BUF_A, W1_OFF, emb_b1, BUF_C, NN, H512, 64, 1);      // -> bufC
    fastgemm(BUF_C, W2_OFF, emb_b2, BUF_B, NN, H512, H512, 1);    // h -> bufB

    // conv1: aggregate (512) then transform
    k_gather<<<NN, H512 / 8>>>(BUF_B, BUF_C, H512 / 8);           // agg(h) -> bufC
    fastgemm(BUF_C, C6_OFF, c6_b, BUF_A, NN, H1024, H512, 1);     // h1 -> bufA

    // conv2
    k_gather<<<NN, H1024 / 8>>>(BUF_A, BUF_C, H1024 / 8);
    fastgemm(BUF_C, C7_OFF, c7_b, BUF_B, NN, H1024, H1024, 1);    // h2 -> bufB

    // conv3
    k_gather<<<NN, H1024 / 8>>>(BUF_B, BUF_A, H1024 / 8);
    fastgemm(BUF_A, C8_OFF, c8_b, BUF_C, NN, H1024, H1024, 1);    // h3 -> bufC

    // mean pool
    dim3 pgrid(GG, H1024 / 256);
    k_pool2<<<pgrid, 256>>>(BUF_C, batch);

    // head
    fastgemm(BUF_POOLED, FC1_OFF, fc1_b, BUF_Z, GG, FC, H1024, 1); // z
    k_head<<<GG, 384>>>(head_w, head_b, out);
}

// round 16
// speedup vs baseline: 2.0262x; 1.0201x over previous
#include <cuda_runtime.h>
#include <cuda_fp16.h>
#include <cstdint>

#define NN    50000
#define EE    200000
#define GG    128
#define FIN   40
#define H512  512
#define H1024 1024
#define FC    2048
#define NCLS  345
#define NB_SCAN ((NN + 255) / 256)

// fp16 transposed weight scratch offsets (halves); layout [N][Kpad]
#define W1_OFF   0
#define W2_OFF   32768
#define C6_OFF   294912
#define C7_OFF   819200
#define C8_OFF   1867776
#define FC1_OFF  2916352
#define WH_TOTAL 5013504

// dynamic smem: As[4][128][40] + Bs[4][256][40] halves (4-stage pipeline)
#define AS_BUF   (128 * 40)
#define BS_BUF   (256 * 40)
#define N_STAGE  4
#define AS_HALFS (N_STAGE * AS_BUF)
#define BS_HALFS (N_STAGE * BS_BUF)
#define FG_SMEM ((AS_HALFS + BS_HALFS) * 2)

// ---------------- scratch (static device globals; no allocations) ----------
__device__ __half g_bufA[(size_t)NN * H1024];
__device__ __half g_bufB[(size_t)NN * H1024];
__device__ __half g_bufC[(size_t)NN * H1024];
__device__ __half g_wh[WH_TOTAL];
__device__ __half g_pooled[GG * H1024];
__device__ __half g_z[GG * FC];
__device__ float g_ew[EE];
__device__ float g_deg[NN];
__device__ float g_dis[NN];
__device__ int   g_is64;

// CSR (by destination); interleaved {src, w} per edge
__device__ int   g_ecnt[NN];
__device__ int   g_rowstart[NN];
__device__ int   g_next[NN];
__device__ uint2 g_csr[EE];          // .x = src, .y = bits of float w
__device__ int   g_blksum[NB_SCAN];

#define BUF_A      0
#define BUF_B      1
#define BUF_C      2
#define BUF_POOLED 3
#define BUF_Z      4
__device__ __forceinline__ __half* sel(int id) {
    switch (id) {
        case BUF_A:      return g_bufA;
        case BUF_B:      return g_bufB;
        case BUF_C:      return g_bufC;
        case BUF_POOLED: return g_pooled;
        case BUF_Z:      return g_z;
    }
    return nullptr;
}

__device__ __forceinline__ int ld_idx(const void* p, long long i) {
    return g_is64 ? (int)((const long long*)p)[i] : ((const int*)p)[i];
}

#define CP_ASYNC16(dst_u32, src_ptr) \
    asm volatile("cp.async.ca.shared.global [%0], [%1], 16;\n" :: "r"(dst_u32), "l"(src_ptr))
#define CP_COMMIT() asm volatile("cp.async.commit_group;\n" ::: "memory")
#define CP_WAIT0()  asm volatile("cp.async.wait_group 0;\n" ::: "memory")
#define CP_WAIT1()  asm volatile("cp.async.wait_group 1;\n" ::: "memory")
#define CP_WAIT2()  asm volatile("cp.async.wait_group 2;\n" ::: "memory")

#define LDSM_X4(r0, r1, r2, r3, a) \
    asm volatile("ldmatrix.sync.aligned.m8n8.x4.shared.b16 {%0,%1,%2,%3}, [%4];" \
                 : "=r"(r0), "=r"(r1), "=r"(r2), "=r"(r3) : "r"(a))

// ---------------- dtype detection ------------------------------------------
__global__ void k_detect(const unsigned int* __restrict__ ei_words) {
    __shared__ int found;
    if (threadIdx.x == 0) found = 0;
    __syncthreads();
    for (int i = 1 + 2 * threadIdx.x; i < 4096; i += 2 * blockDim.x)
        if (ei_words[i] != 0u) found = 1;
    __syncthreads();
    if (threadIdx.x == 0) g_is64 = (found ? 0 : 1);
}

__global__ void k_init() {
    int i = blockIdx.x * blockDim.x + threadIdx.x;
    if (i < NN) { g_deg[i] = 1.0f; g_ecnt[i] = 0; }
}

// ---------------- coalesced weight transpose + fp16 convert ------------------
__global__ void k_wtT(const float* __restrict__ src, int off, int K, int Kpad, int N) {
    __shared__ float t[32][33];
    int k0 = blockIdx.x * 32;
    int n0 = blockIdx.y * 32;
    int tx = threadIdx.x, ty = threadIdx.y;    // 32 x 8
#pragma unroll
    for (int i = 0; i < 4; i++) {
        int k = k0 + ty + i * 8;
        int n = n0 + tx;
        t[ty + i * 8][tx] = (k < K) ? src[(size_t)k * N + n] : 0.0f;
    }
    __syncthreads();
#pragma unroll
    for (int i = 0; i < 4; i++) {
        int n = n0 + ty + i * 8;
        int k = k0 + tx;
        g_wh[off + (size_t)n * Kpad + k] = __float2half_rn(t[tx][ty + i * 8]);
    }
}

// ---------------- pad x: [NN][40] fp32 -> bufA [NN][64] fp16 ----------------
__global__ void k_padx(const float* __restrict__ x) {
    int i = blockIdx.x * 256 + threadIdx.x;
    if (i >= NN * 64) return;
    int row = i >> 6, c = i & 63;
    float v = (c < FIN) ? x[(size_t)row * FIN + c] : 0.0f;
    g_bufA[i] = __float2half_rn(v);
}

// ---------------- edge MLP + weighted degree + in-edge count (fused) --------
__global__ void k_edge_mlp_deg(const float* __restrict__ ea,
                               const float* __restrict__ w1, const float* __restrict__ b1,
                               const float* __restrict__ w2, const float* __restrict__ b2,
                               const void* __restrict__ ei) {
    int e = blockIdx.x * blockDim.x + threadIdx.x;
    if (e >= EE) return;
    float a0 = ea[e * 3 + 0], a1 = ea[e * 3 + 1], a2 = ea[e * 3 + 2];
    float acc = b2[0];
#pragma unroll 8
    for (int h = 0; h < 64; h++) {
        float v = b1[h] + a0 * w1[h] + a1 * w1[64 + h] + a2 * w1[128 + h];
        acc += fmaxf(v, 0.0f) * w2[h];
    }
    float ew = 1.0f / (1.0f + expf(-acc));
    g_ew[e] = ew;
    int d = ld_idx(ei, (long long)EE + e);
    if (d >= 0 && d < NN) {
        atomicAdd(&g_deg[d], ew);
        atomicAdd(&g_ecnt[d], 1);
    }
}

// ---------------- CSR build (dis fused into scan_block) ----------------------
__global__ void k_scan_block() {
    __shared__ int s[256];
    int tid = threadIdx.x;
    int i = blockIdx.x * 256 + tid;
    if (i < NN) g_dis[i] = rsqrtf(g_deg[i]);
    int v = (i < NN) ? g_ecnt[i] : 0;
    s[tid] = v;
    __syncthreads();
#pragma unroll
    for (int off = 1; off < 256; off <<= 1) {
        int t = (tid >= off) ? s[tid - off] : 0;
        __syncthreads();
        s[tid] += t;
        __syncthreads();
    }
    if (i < NN) g_rowstart[i] = s[tid] - v;
    if (tid == 255) g_blksum[blockIdx.x] = s[tid];
}

__global__ void k_scan_tops() {
    __shared__ int s[256];
    int tid = threadIdx.x;
    int v = (tid < NB_SCAN) ? g_blksum[tid] : 0;
    s[tid] = v;
    __syncthreads();
#pragma unroll
    for (int off = 1; off < 256; off <<= 1) {
        int t = (tid >= off) ? s[tid - off] : 0;
        __syncthreads();
        s[tid] += t;
        __syncthreads();
    }
    if (tid < NB_SCAN) g_blksum[tid] = s[tid] - v;
}

__global__ void k_scan_add() {
    int i = blockIdx.x * 256 + threadIdx.x;
    if (i >= NN) return;
    int r = g_rowstart[i] + g_blksum[blockIdx.x];
    g_rowstart[i] = r;
    g_next[i] = r;
}

__global__ void k_fill(const void* __restrict__ ei) {
    int e = blockIdx.x * blockDim.x + threadIdx.x;
    if (e >= EE) return;
    int s = ld_idx(ei, e);
    int d = ld_idx(ei, (long long)EE + e);
    if (s < 0 || s >= NN || d < 0 || d >= NN) return;
    int pos = atomicAdd(&g_next[d], 1);
    uint2 rec;
    rec.x = (unsigned)s;
    rec.y = __float_as_uint(g_dis[s] * g_ew[e] * g_dis[d]);
    g_csr[pos] = rec;
}

// ---------------- FAST fp16 GEMM: 4-stage cp.async + ldmatrix ----------------
// CTA 128x256, 8 warps 64x64, BK=32, mma.m16n8k16 fp32 accum. K%32==0, N%256==0.
__global__ __launch_bounds__(256) void k_fastgemm(
    int aId, int bOff, const float* __restrict__ bias, int cId,
    int M, int N, int K, int doRelu)
{
    extern __shared__ __half smemH[];
    const __half* __restrict__ A = sel(aId);
    const __half* __restrict__ B = g_wh + bOff;
    __half* __restrict__ C       = sel(cId);

    const int tid  = threadIdx.x;
    const int wid  = tid >> 5;
    const int lane = tid & 31;
    const int grp  = lane >> 2;
    const int tg   = lane & 3;
    const int warp_m = wid & 1;
    const int warp_n = wid >> 1;

    const int blockRow = blockIdx.y * 128;
    const int blockCol = blockIdx.x * 256;

    float acc[4][8][4];
#pragma unroll
    for (int mi = 0; mi < 4; mi++)
#pragma unroll
        for (int ni = 0; ni < 8; ni++)
#pragma unroll
            for (int r = 0; r < 4; r++) acc[mi][ni][r] = 0.0f;

    const int T = K >> 5;

    uint32_t asU = (uint32_t)__cvta_generic_to_shared(smemH);
    uint32_t bsU = asU + AS_HALFS * 2;

    const int aLaneOff = (lane & 15) * 40 + (lane >> 4) * 8;
    const int bLaneOff = ((lane & 7) + (lane >> 4) * 8) * 40 + ((lane >> 3) & 1) * 8;

    auto load_tile = [&](int it, int buf) {
        const int k0 = it << 5;
        uint32_t aB = asU + buf * (AS_BUF * 2);
        uint32_t bB = bsU + buf * (BS_BUF * 2);
#pragma unroll
        for (int i = 0; i < 2; i++) {
            int q = tid + i * 256;
            int row = q >> 2, c = q & 3;
            int gr = min(blockRow + row, M - 1);
            CP_ASYNC16(aB + row * 80 + c * 16, A + (size_t)gr * K + k0 + c * 8);
        }
#pragma unroll
        for (int i = 0; i < 4; i++) {
            int q = tid + i * 256;
            int row = q >> 2, c = q & 3;
            CP_ASYNC16(bB + row * 80 + c * 16, B + (size_t)(blockCol + row) * K + k0 + c * 8);
        }
        CP_COMMIT();
    };

    load_tile(0, 0);
    if (T > 1) load_tile(1, 1);
    if (T > 2) load_tile(2, 2);

    for (int it = 0; it < T; it++) {
        const int buf = it & 3;
        const int rem = T - 1 - it;
        if (rem >= 2) CP_WAIT2();
        else if (rem == 1) CP_WAIT1();
        else CP_WAIT0();
        __syncthreads();
        if (it + 3 < T) load_tile(it + 3, (it + 3) & 3);

        uint32_t aB = asU + buf * (AS_BUF * 2);
        uint32_t bB = bsU + buf * (BS_BUF * 2);
#pragma unroll
        for (int ks = 0; ks < 2; ks++) {
            const int kb = ks * 16;
            uint32_t af[4][4], bf[8][2];
#pragma unroll
            for (int mi = 0; mi < 4; mi++) {
                int rb = warp_m * 64 + mi * 16;
                uint32_t addr = aB + (rb * 40 + kb + aLaneOff) * 2;
                LDSM_X4(af[mi][0], af[mi][1], af[mi][2], af[mi][3], addr);
            }
#pragma unroll
            for (int nj = 0; nj < 4; nj++) {
                int nb = warp_n * 64 + nj * 16;
                uint32_t addr = bB + (nb * 40 + kb + bLaneOff) * 2;
                LDSM_X4(bf[2 * nj][0], bf[2 * nj][1], bf[2 * nj + 1][0], bf[2 * nj + 1][1], addr);
            }
#pragma unroll
            for (int mi = 0; mi < 4; mi++)
#pragma unroll
                for (int ni = 0; ni < 8; ni++) {
                    asm volatile(
                        "mma.sync.aligned.m16n8k16.row.col.f32.f16.f16.f32 "
                        "{%0,%1,%2,%3}, {%4,%5,%6,%7}, {%8,%9}, {%0,%1,%2,%3};\n"
                        : "+f"(acc[mi][ni][0]), "+f"(acc[mi][ni][1]),
                          "+f"(acc[mi][ni][2]), "+f"(acc[mi][ni][3])
                        : "r"(af[mi][0]), "r"(af[mi][1]), "r"(af[mi][2]), "r"(af[mi][3]),
                          "r"(bf[ni][0]), "r"(bf[ni][1]));
                }
        }
    }

#pragma unroll
    for (int mi = 0; mi < 4; mi++) {
        int r0 = blockRow + warp_m * 64 + mi * 16 + grp;
        int r1 = r0 + 8;
#pragma unroll
        for (int ni = 0; ni < 8; ni++) {
            int c0 = blockCol + warp_n * 64 + ni * 8 + 2 * tg;
            float b0 = bias[c0], b1 = bias[c0 + 1];
            if (r0 < M) {
                float v0 = acc[mi][ni][0] + b0;
                float v1 = acc[mi][ni][1] + b1;
                if (doRelu) { v0 = fmaxf(v0, 0.0f); v1 = fmaxf(v1, 0.0f); }
                *(__half2*)(C + (size_t)r0 * N + c0) = __floats2half2_rn(v0, v1);
            }
            if (r1 < M) {
                float v0 = acc[mi][ni][2] + b0;
                float v1 = acc[mi][ni][3] + b1;
                if (doRelu) { v0 = fmaxf(v0, 0.0f); v1 = fmaxf(v1, 0.0f); }
                *(__half2*)(C + (size_t)r1 * N + c0) = __floats2half2_rn(v0, v1);
            }
        }
    }
}

// ---------------- gather: out[n,:] = h2(dis^2 t[n,:] + sum w t[src,:]) -------
__global__ void k_gather(int tId, int outId, int Fo) {
    const uint4* __restrict__ t4 = (const uint4*)sel(tId);
    uint4* __restrict__ o4       = (uint4*)sel(outId);

    int node = blockIdx.x;
    int tid  = threadIdx.x;

    float d = g_dis[node];
    float sw = d * d;
    uint4 u = t4[(size_t)node * Fo + tid];
    const __half2* uh = (const __half2*)&u;
    float a[8];
#pragma unroll
    for (int j = 0; j < 4; j++) {
        float2 p = __half22float2(uh[j]);
        a[2 * j] = sw * p.x; a[2 * j + 1] = sw * p.y;
    }

    int s = g_rowstart[node];
    int e = s + g_ecnt[node];
    int i = s;
    for (; i + 1 < e; i += 2) {
        uint2 r0 = g_csr[i];
        uint2 r1 = g_csr[i + 1];
        float w0 = __uint_as_float(r0.y);
        float w1 = __uint_as_float(r1.y);
        uint4 v0 = t4[(size_t)r0.x * Fo + tid];
        uint4 v1 = t4[(size_t)r1.x * Fo + tid];
        const __half2* vh0 = (const __half2*)&v0;
        const __half2* vh1 = (const __half2*)&v1;
#pragma unroll
        for (int j = 0; j < 4; j++) {
            float2 q0 = __half22float2(vh0[j]);
            float2 q1 = __half22float2(vh1[j]);
            a[2 * j]     += w0 * q0.x + w1 * q1.x;
            a[2 * j + 1] += w0 * q0.y + w1 * q1.y;
        }
    }
    if (i < e) {
        uint2 r0 = g_csr[i];
        float w0 = __uint_as_float(r0.y);
        uint4 v0 = t4[(size_t)r0.x * Fo + tid];
        const __half2* vh0 = (const __half2*)&v0;
#pragma unroll
        for (int j = 0; j < 4; j++) {
            float2 q0 = __half22float2(vh0[j]);
            a[2 * j] += w0 * q0.x; a[2 * j + 1] += w0 * q0.y;
        }
    }
    uint4 o;
    __half2* oh = (__half2*)&o;
#pragma unroll
    for (int j = 0; j < 4; j++)
        oh[j] = __floats2half2_rn(a[2 * j], a[2 * j + 1]);
    o4[(size_t)node * Fo + tid] = o;
}

// ---------------- segmented mean pooling (batch sorted) ----------------------
__global__ void k_pool2(int hId, const void* __restrict__ batch) {
    const __half* __restrict__ h = sel(hId);
    int g = blockIdx.x;
    int f = blockIdx.y * 256 + threadIdx.x;

    int lo = 0, hi = NN;
    while (lo < hi) { int mid = (lo + hi) >> 1; if (ld_idx(batch, mid) < g) lo = mid + 1; else hi = mid; }
    int start = lo;
    lo = start; hi = NN;
    while (lo < hi) { int mid = (lo + hi) >> 1; if (ld_idx(batch, mid) < g + 1) lo = mid + 1; else hi = mid; }
    int end = lo;

    float acc = 0.0f;
    for (int n = start; n < end; n++)
        acc += __half2float(h[(size_t)n * H1024 + f]);
    float cnt = (float)(end - start);
    g_pooled[g * H1024 + f] = __float2half_rn(acc / fmaxf(cnt, 1.0f));
}

// ---------------- head: out[g,j] = head_b[j] + dot(z[g,:], head_w[:,j]) -----
__global__ __launch_bounds__(384) void k_head(const float* __restrict__ hw,
                                              const float* __restrict__ hb,
                                              float* __restrict__ out) {
    __shared__ float zs[FC];
    int g = blockIdx.x;
    for (int k = threadIdx.x; k < FC; k += blockDim.x)
        zs[k] = __half2float(g_z[(size_t)g * FC + k]);
    __syncthreads();
    int j = threadIdx.x;
    if (j >= NCLS) return;
    float acc = hb[j];
#pragma unroll 8
    for (int k = 0; k < FC; k++)
        acc = fmaf(zs[k], hw[(size_t)k * NCLS + j], acc);
    out[(size_t)g * NCLS + j] = acc;
}

// ---------------- host orchestration ---------------------------------------
static void fastgemm(int aId, int bOff, const float* bias, int cId,
                     int M, int N, int K, int relu) {
    dim3 grid(N / 256, (M + 127) / 128);
    k_fastgemm<<<grid, 256, FG_SMEM>>>(aId, bOff, bias, cId, M, N, K, relu);
}
static void wtT(const float* src, int off, int K, int Kpad, int N, cudaStream_t st) {
    dim3 grid(Kpad / 32, N / 32);
    k_wtT<<<grid, dim3(32, 8), 0, st>>>(src, off, K, Kpad, N);
}

extern "C" void kernel_launch(void* const* d_in, const int* in_sizes, int n_in,
                              void* d_out, int out_size) {
    const float* x         = (const float*)d_in[0];
    const float* edge_attr = (const float*)d_in[1];
    const void*  ei        = d_in[2];
    const void*  batch     = d_in[3];
    const float *emb_w1 = (const float*)d_in[4],  *emb_b1 = (const float*)d_in[5];
    const float *emb_w2 = (const float*)d_in[6],  *emb_b2 = (const float*)d_in[7];
    const float *ep_w1  = (const float*)d_in[8],  *ep_b1  = (const float*)d_in[9];
    const float *ep_w2  = (const float*)d_in[10], *ep_b2  = (const float*)d_in[11];
    const float *c6_w   = (const float*)d_in[12], *c6_b   = (const float*)d_in[13];
    const float *c7_w   = (const float*)d_in[14], *c7_b   = (const float*)d_in[15];
    const float *c8_w   = (const float*)d_in[16], *c8_b   = (const float*)d_in[17];
    const float *fc1_w  = (const float*)d_in[18], *fc1_b  = (const float*)d_in[19];
    const float *head_w = (const float*)d_in[20], *head_b = (const float*)d_in[21];
    float* out = (float*)d_out;

    static cudaStream_t sSide = nullptr;
    static cudaEvent_t evFork = nullptr, evJoin = nullptr;
    if (!sSide) {
        cudaStreamCreateWithFlags(&sSide, cudaStreamNonBlocking);
        cudaEventCreateWithFlags(&evFork, cudaEventDisableTiming);
        cudaEventCreateWithFlags(&evJoin, cudaEventDisableTiming);
        cudaFuncSetAttribute(k_fastgemm, cudaFuncAttributeMaxDynamicSharedMemorySize, FG_SMEM);
    }

    // ---- main stream: dtype detection (needed by both branches) ----
    k_detect<<<1, 256>>>((const unsigned int*)ei);

    // ---- fork: CSR build + conv/fc weight transposes on side stream ----
    cudaEventRecord(evFork, 0);
    cudaStreamWaitEvent(sSide, evFork, 0);

    k_init<<<NB_SCAN, 256, 0, sSide>>>();
    k_edge_mlp_deg<<<(EE + 255) / 256, 256, 0, sSide>>>(edge_attr, ep_w1, ep_b1, ep_w2, ep_b2, ei);
    k_scan_block<<<NB_SCAN, 256, 0, sSide>>>();   // also computes dis
    k_scan_tops<<<1, 256, 0, sSide>>>();
    k_scan_add<<<NB_SCAN, 256, 0, sSide>>>();
    k_fill<<<(EE + 255) / 256, 256, 0, sSide>>>(ei);
    wtT(c6_w, C6_OFF, H512, H512, H1024, sSide);
    wtT(c7_w, C7_OFF, H1024, H1024, H1024, sSide);
    wtT(c8_w, C8_OFF, H1024, H1024, H1024, sSide);
    wtT(fc1_w, FC1_OFF, H1024, H1024, FC, sSide);
    cudaEventRecord(evJoin, sSide);

    // ---- main stream: embedding path (independent of CSR) ----
    k_padx<<<(NN * 64 + 255) / 256, 256>>>(x);
    wtT(emb_w1, W1_OFF, FIN, 64, H512, 0);
    wtT(emb_w2, W2_OFF, H512, H512, H512, 0);
    fastgemm(BUF_A, W1_OFF, emb_b1, BUF_C, NN, H512, 64, 1);      // -> bufC
    fastgemm(BUF_C, W2_OFF, emb_b2, BUF_B, NN, H512, H512, 1);    // h -> bufB

    // ---- join: CSR + conv weights ready ----
    cudaStreamWaitEvent(0, evJoin, 0);

    // conv1: aggregate (512) then transform
    k_gather<<<NN, H512 / 8>>>(BUF_B, BUF_C, H512 / 8);           // agg(h) -> bufC
    fastgemm(BUF_C, C6_OFF, c6_b, BUF_A, NN, H1024, H512, 1);     // h1 -> bufA

    // conv2
    k_gather<<<NN, H1024 / 8>>>(BUF_A, BUF_C, H1024 / 8);
    fastgemm(BUF_C, C7_OFF, c7_b, BUF_B, NN, H1024, H1024, 1);    // h2 -> bufB

    // conv3
    k_gather<<<NN, H1024 / 8>>>(BUF_B, BUF_A, H1024 / 8);
    fastgemm(BUF_A, C8_OFF, c8_b, BUF_C, NN, H1024, H1024, 1);    // h3 -> bufC

    // mean pool
    dim3 pgrid(GG, H1024 / 256);
    k_pool2<<<pgrid, 256>>>(BUF_C, batch);

    // head
    fastgemm(BUF_POOLED, FC1_OFF, fc1_b, BUF_Z, GG, FC, H1024, 1); // z
    k_head<<<GG, 384>>>(head_w, head_b, out);
}

// round 17
// speedup vs baseline: 2.1032x; 1.0380x over previous
#include <cuda_runtime.h>
#include <cuda_fp16.h>
#include <cstdint>

#define NN    50000
#define EE    200000
#define GG    128
#define FIN   40
#define H512  512
#define H1024 1024
#define FC    2048
#define NCLS  345
#define NB_SCAN ((NN + 255) / 256)

// fp16 transposed weight scratch offsets (halves); layout [N][Kpad]
#define W1_OFF   0
#define W2_OFF   32768
#define C6_OFF   294912
#define C7_OFF   819200
#define C8_OFF   1867776
#define FC1_OFF  2916352
#define WH_TOTAL 5013504

// dynamic smem: As[4][128][40] + Bs[4][256][40] halves (4-stage pipeline)
// epilogue reuses the same smem as a 128x264 fp16 staging tile (67.6KB < 122.9KB)
#define AS_BUF   (128 * 40)
#define BS_BUF   (256 * 40)
#define N_STAGE  4
#define AS_HALFS (N_STAGE * AS_BUF)
#define BS_HALFS (N_STAGE * BS_BUF)
#define FG_SMEM ((AS_HALFS + BS_HALFS) * 2)
#define CT_STRIDE 264

// ---------------- scratch (static device globals; no allocations) ----------
__device__ __half g_bufA[(size_t)NN * H1024];
__device__ __half g_bufB[(size_t)NN * H1024];
__device__ __half g_bufC[(size_t)NN * H1024];
__device__ __half g_wh[WH_TOTAL];
__device__ __half g_pooled[GG * H1024];
__device__ __half g_z[GG * FC];
__device__ float g_ew[EE];
__device__ float g_deg[NN];
__device__ float g_dis[NN];
__device__ int   g_is64;

// CSR (by destination); interleaved {src, w} per edge
__device__ int   g_ecnt[NN];
__device__ int   g_rowstart[NN];
__device__ int   g_next[NN];
__device__ uint2 g_csr[EE];          // .x = src, .y = bits of float w
__device__ int   g_blksum[NB_SCAN];

#define BUF_A      0
#define BUF_B      1
#define BUF_C      2
#define BUF_POOLED 3
#define BUF_Z      4
__device__ __forceinline__ __half* sel(int id) {
    switch (id) {
        case BUF_A:      return g_bufA;
        case BUF_B:      return g_bufB;
        case BUF_C:      return g_bufC;
        case BUF_POOLED: return g_pooled;
        case BUF_Z:      return g_z;
    }
    return nullptr;
}

__device__ __forceinline__ int ld_idx(const void* p, long long i) {
    return g_is64 ? (int)((const long long*)p)[i] : ((const int*)p)[i];
}

#define CP_ASYNC16(dst_u32, src_ptr) \
    asm volatile("cp.async.ca.shared.global [%0], [%1], 16;\n" :: "r"(dst_u32), "l"(src_ptr))
#define CP_COMMIT() asm volatile("cp.async.commit_group;\n" ::: "memory")
#define CP_WAIT0()  asm volatile("cp.async.wait_group 0;\n" ::: "memory")
#define CP_WAIT1()  asm volatile("cp.async.wait_group 1;\n" ::: "memory")
#define CP_WAIT2()  asm volatile("cp.async.wait_group 2;\n" ::: "memory")

#define LDSM_X4(r0, r1, r2, r3, a) \
    asm volatile("ldmatrix.sync.aligned.m8n8.x4.shared.b16 {%0,%1,%2,%3}, [%4];" \
                 : "=r"(r0), "=r"(r1), "=r"(r2), "=r"(r3) : "r"(a))

// ---------------- dtype detection ------------------------------------------
__global__ void k_detect(const unsigned int* __restrict__ ei_words) {
    __shared__ int found;
    if (threadIdx.x == 0) found = 0;
    __syncthreads();
    for (int i = 1 + 2 * threadIdx.x; i < 4096; i += 2 * blockDim.x)
        if (ei_words[i] != 0u) found = 1;
    __syncthreads();
    if (threadIdx.x == 0) g_is64 = (found ? 0 : 1);
}

__global__ void k_init() {
    int i = blockIdx.x * blockDim.x + threadIdx.x;
    if (i < NN) { g_deg[i] = 1.0f; g_ecnt[i] = 0; }
}

// ---------------- coalesced weight transpose + fp16 convert ------------------
__global__ void k_wtT(const float* __restrict__ src, int off, int K, int Kpad, int N) {
    __shared__ float t[32][33];
    int k0 = blockIdx.x * 32;
    int n0 = blockIdx.y * 32;
    int tx = threadIdx.x, ty = threadIdx.y;    // 32 x 8
#pragma unroll
    for (int i = 0; i < 4; i++) {
        int k = k0 + ty + i * 8;
        int n = n0 + tx;
        t[ty + i * 8][tx] = (k < K) ? src[(size_t)k * N + n] : 0.0f;
    }
    __syncthreads();
#pragma unroll
    for (int i = 0; i < 4; i++) {
        int n = n0 + ty + i * 8;
        int k = k0 + tx;
        g_wh[off + (size_t)n * Kpad + k] = __float2half_rn(t[tx][ty + i * 8]);
    }
}

// ---------------- pad x: [NN][40] fp32 -> bufA [NN][64] fp16 ----------------
__global__ void k_padx(const float* __restrict__ x) {
    int i = blockIdx.x * 256 + threadIdx.x;
    if (i >= NN * 64) return;
    int row = i >> 6, c = i & 63;
    float v = (c < FIN) ? x[(size_t)row * FIN + c] : 0.0f;
    g_bufA[i] = __float2half_rn(v);
}

// ---------------- edge MLP + weighted degree + in-edge count (fused) --------
__global__ void k_edge_mlp_deg(const float* __restrict__ ea,
                               const float* __restrict__ w1, const float* __restrict__ b1,
                               const float* __restrict__ w2, const float* __restrict__ b2,
                               const void* __restrict__ ei) {
    int e = blockIdx.x * blockDim.x + threadIdx.x;
    if (e >= EE) return;
    float a0 = ea[e * 3 + 0], a1 = ea[e * 3 + 1], a2 = ea[e * 3 + 2];
    float acc = b2[0];
#pragma unroll 8
    for (int h = 0; h < 64; h++) {
        float v = b1[h] + a0 * w1[h] + a1 * w1[64 + h] + a2 * w1[128 + h];
        acc += fmaxf(v, 0.0f) * w2[h];
    }
    float ew = 1.0f / (1.0f + expf(-acc));
    g_ew[e] = ew;
    int d = ld_idx(ei, (long long)EE + e);
    if (d >= 0 && d < NN) {
        atomicAdd(&g_deg[d], ew);
        atomicAdd(&g_ecnt[d], 1);
    }
}

// ---------------- CSR build (dis fused into scan_block) ----------------------
__global__ void k_scan_block() {
    __shared__ int s[256];
    int tid = threadIdx.x;
    int i = blockIdx.x * 256 + tid;
    if (i < NN) g_dis[i] = rsqrtf(g_deg[i]);
    int v = (i < NN) ? g_ecnt[i] : 0;
    s[tid] = v;
    __syncthreads();
#pragma unroll
    for (int off = 1; off < 256; off <<= 1) {
        int t = (tid >= off) ? s[tid - off] : 0;
        __syncthreads();
        s[tid] += t;
        __syncthreads();
    }
    if (i < NN) g_rowstart[i] = s[tid] - v;
    if (tid == 255) g_blksum[blockIdx.x] = s[tid];
}

__global__ void k_scan_tops() {
    __shared__ int s[256];
    int tid = threadIdx.x;
    int v = (tid < NB_SCAN) ? g_blksum[tid] : 0;
    s[tid] = v;
    __syncthreads();
#pragma unroll
    for (int off = 1; off < 256; off <<= 1) {
        int t = (tid >= off) ? s[tid - off] : 0;
        __syncthreads();
        s[tid] += t;
        __syncthreads();
    }
    if (tid < NB_SCAN) g_blksum[tid] = s[tid] - v;
}

__global__ void k_scan_add() {
    int i = blockIdx.x * 256 + threadIdx.x;
    if (i >= NN) return;
    int r = g_rowstart[i] + g_blksum[blockIdx.x];
    g_rowstart[i] = r;
    g_next[i] = r;
}

__global__ void k_fill(const void* __restrict__ ei) {
    int e = blockIdx.x * blockDim.x + threadIdx.x;
    if (e >= EE) return;
    int s = ld_idx(ei, e);
    int d = ld_idx(ei, (long long)EE + e);
    if (s < 0 || s >= NN || d < 0 || d >= NN) return;
    int pos = atomicAdd(&g_next[d], 1);
    uint2 rec;
    rec.x = (unsigned)s;
    rec.y = __float_as_uint(g_dis[s] * g_ew[e] * g_dis[d]);
    g_csr[pos] = rec;
}

// ---------------- FAST fp16 GEMM: 4-stage cp.async + ldmatrix ----------------
// CTA 128x256, 8 warps 64x64, BK=32, mma.m16n8k16 fp32 accum. K%32==0, N%256==0.
// Epilogue stages the output tile in smem for fully coalesced global stores.
__global__ __launch_bounds__(256) void k_fastgemm(
    int aId, int bOff, const float* __restrict__ bias, int cId,
    int M, int N, int K, int doRelu)
{
    extern __shared__ __half smemH[];
    const __half* __restrict__ A = sel(aId);
    const __half* __restrict__ B = g_wh + bOff;
    __half* __restrict__ C       = sel(cId);

    const int tid  = threadIdx.x;
    const int wid  = tid >> 5;
    const int lane = tid & 31;
    const int grp  = lane >> 2;
    const int tg   = lane & 3;
    const int warp_m = wid & 1;
    const int warp_n = wid >> 1;

    const int blockRow = blockIdx.y * 128;
    const int blockCol = blockIdx.x * 256;

    float acc[4][8][4];
#pragma unroll
    for (int mi = 0; mi < 4; mi++)
#pragma unroll
        for (int ni = 0; ni < 8; ni++)
#pragma unroll
            for (int r = 0; r < 4; r++) acc[mi][ni][r] = 0.0f;

    const int T = K >> 5;

    uint32_t asU = (uint32_t)__cvta_generic_to_shared(smemH);
    uint32_t bsU = asU + AS_HALFS * 2;

    const int aLaneOff = (lane & 15) * 40 + (lane >> 4) * 8;
    const int bLaneOff = ((lane & 7) + (lane >> 4) * 8) * 40 + ((lane >> 3) & 1) * 8;

    auto load_tile = [&](int it, int buf) {
        const int k0 = it << 5;
        uint32_t aB = asU + buf * (AS_BUF * 2);
        uint32_t bB = bsU + buf * (BS_BUF * 2);
#pragma unroll
        for (int i = 0; i < 2; i++) {
            int q = tid + i * 256;
            int row = q >> 2, c = q & 3;
            int gr = min(blockRow + row, M - 1);
            CP_ASYNC16(aB + row * 80 + c * 16, A + (size_t)gr * K + k0 + c * 8);
        }
#pragma unroll
        for (int i = 0; i < 4; i++) {
            int q = tid + i * 256;
            int row = q >> 2, c = q & 3;
            CP_ASYNC16(bB + row * 80 + c * 16, B + (size_t)(blockCol + row) * K + k0 + c * 8);
        }
        CP_COMMIT();
    };

    load_tile(0, 0);
    if (T > 1) load_tile(1, 1);
    if (T > 2) load_tile(2, 2);

    for (int it = 0; it < T; it++) {
        const int buf = it & 3;
        const int rem = T - 1 - it;
        if (rem >= 2) CP_WAIT2();
        else if (rem == 1) CP_WAIT1();
        else CP_WAIT0();
        __syncthreads();
        if (it + 3 < T) load_tile(it + 3, (it + 3) & 3);

        uint32_t aB = asU + buf * (AS_BUF * 2);
        uint32_t bB = bsU + buf * (BS_BUF * 2);
#pragma unroll
        for (int ks = 0; ks < 2; ks++) {
            const int kb = ks * 16;
            uint32_t af[4][4], bf[8][2];
#pragma unroll
            for (int mi = 0; mi < 4; mi++) {
                int rb = warp_m * 64 + mi * 16;
                uint32_t addr = aB + (rb * 40 + kb + aLaneOff) * 2;
                LDSM_X4(af[mi][0], af[mi][1], af[mi][2], af[mi][3], addr);
            }
#pragma unroll
            for (int nj = 0; nj < 4; nj++) {
                int nb = warp_n * 64 + nj * 16;
                uint32_t addr = bB + (nb * 40 + kb + bLaneOff) * 2;
                LDSM_X4(bf[2 * nj][0], bf[2 * nj][1], bf[2 * nj + 1][0], bf[2 * nj + 1][1], addr);
            }
#pragma unroll
            for (int mi = 0; mi < 4; mi++)
#pragma unroll
                for (int ni = 0; ni < 8; ni++) {
                    asm volatile(
                        "mma.sync.aligned.m16n8k16.row.col.f32.f16.f16.f32 "
                        "{%0,%1,%2,%3}, {%4,%5,%6,%7}, {%8,%9}, {%0,%1,%2,%3};\n"
                        : "+f"(acc[mi][ni][0]), "+f"(acc[mi][ni][1]),
                          "+f"(acc[mi][ni][2]), "+f"(acc[mi][ni][3])
                        : "r"(af[mi][0]), "r"(af[mi][1]), "r"(af[mi][2]), "r"(af[mi][3]),
                          "r"(bf[ni][0]), "r"(bf[ni][1]));
                }
        }
    }

    // ---- epilogue: stage bias+relu'd fp16 tile in smem, then coalesced copy ----
    __syncthreads();   // all warps finished reading pipeline smem
    __half* ct = smemH;   // 128 x CT_STRIDE halves

#pragma unroll
    for (int mi = 0; mi < 4; mi++) {
        int r0 = warp_m * 64 + mi * 16 + grp;
        int r1 = r0 + 8;
#pragma unroll
        for (int ni = 0; ni < 8; ni++) {
            int c0 = warp_n * 64 + ni * 8 + 2 * tg;
            float b0 = bias[blockCol + c0], b1 = bias[blockCol + c0 + 1];
            {
                float v0 = acc[mi][ni][0] + b0;
                float v1 = acc[mi][ni][1] + b1;
                if (doRelu) { v0 = fmaxf(v0, 0.0f); v1 = fmaxf(v1, 0.0f); }
                *(__half2*)(ct + r0 * CT_STRIDE + c0) = __floats2half2_rn(v0, v1);
            }
            {
                float v0 = acc[mi][ni][2] + b0;
                float v1 = acc[mi][ni][3] + b1;
                if (doRelu) { v0 = fmaxf(v0, 0.0f); v1 = fmaxf(v1, 0.0f); }
                *(__half2*)(ct + r1 * CT_STRIDE + c0) = __floats2half2_rn(v0, v1);
            }
        }
    }
    __syncthreads();

    // coalesced copy: 128 rows x 256 halves (32 uint4 per row)
#pragma unroll
    for (int i = 0; i < 16; i++) {
        int q = tid + i * 256;          // 0..4095
        int row = q >> 5;               // 0..127
        int c16 = q & 31;               // uint4 index within row
        int gr = blockRow + row;
        if (gr < M)
            *(uint4*)(C + (size_t)gr * N + blockCol + c16 * 8) =
                *(const uint4*)(ct + row * CT_STRIDE + c16 * 8);
    }
}

// ---------------- gather: out[n,:] = h2(dis^2 t[n,:] + sum w t[src,:]) -------
__global__ void k_gather(int tId, int outId, int Fo) {
    const uint4* __restrict__ t4 = (const uint4*)sel(tId);
    uint4* __restrict__ o4       = (uint4*)sel(outId);

    int node = blockIdx.x;
    int tid  = threadIdx.x;

    float d = g_dis[node];
    float sw = d * d;
    uint4 u = t4[(size_t)node * Fo + tid];
    const __half2* uh = (const __half2*)&u;
    float a[8];
#pragma unroll
    for (int j = 0; j < 4; j++) {
        float2 p = __half22float2(uh[j]);
        a[2 * j] = sw * p.x; a[2 * j + 1] = sw * p.y;
    }

    int s = g_rowstart[node];
    int e = s + g_ecnt[node];
    int i = s;
    for (; i + 1 < e; i += 2) {
        uint2 r0 = g_csr[i];
        uint2 r1 = g_csr[i + 1];
        float w0 = __uint_as_float(r0.y);
        float w1 = __uint_as_float(r1.y);
        uint4 v0 = t4[(size_t)r0.x * Fo + tid];
        uint4 v1 = t4[(size_t)r1.x * Fo + tid];
        const __half2* vh0 = (const __half2*)&v0;
        const __half2* vh1 = (const __half2*)&v1;
#pragma unroll
        for (int j = 0; j < 4; j++) {
            float2 q0 = __half22float2(vh0[j]);
            float2 q1 = __half22float2(vh1[j]);
            a[2 * j]     += w0 * q0.x + w1 * q1.x;
            a[2 * j + 1] += w0 * q0.y + w1 * q1.y;
        }
    }
    if (i < e) {
        uint2 r0 = g_csr[i];
        float w0 = __uint_as_float(r0.y);
        uint4 v0 = t4[(size_t)r0.x * Fo + tid];
        const __half2* vh0 = (const __half2*)&v0;
#pragma unroll
        for (int j = 0; j < 4; j++) {
            float2 q0 = __half22float2(vh0[j]);
            a[2 * j] += w0 * q0.x; a[2 * j + 1] += w0 * q0.y;
        }
    }
    uint4 o;
    __half2* oh = (__half2*)&o;
#pragma unroll
    for (int j = 0; j < 4; j++)
        oh[j] = __floats2half2_rn(a[2 * j], a[2 * j + 1]);
    o4[(size_t)node * Fo + tid] = o;
}

// ---------------- segmented mean pooling (batch sorted) ----------------------
__global__ void k_pool2(int hId, const void* __restrict__ batch) {
    const __half* __restrict__ h = sel(hId);
    int g = blockIdx.x;
    int f = blockIdx.y * 256 + threadIdx.x;

    int lo = 0, hi = NN;
    while (lo < hi) { int mid = (lo + hi) >> 1; if (ld_idx(batch, mid) < g) lo = mid + 1; else hi = mid; }
    int start = lo;
    lo = start; hi = NN;
    while (lo < hi) { int mid = (lo + hi) >> 1; if (ld_idx(batch, mid) < g + 1) lo = mid + 1; else hi = mid; }
    int end = lo;

    float acc = 0.0f;
    for (int n = start; n < end; n++)
        acc += __half2float(h[(size_t)n * H1024 + f]);
    float cnt = (float)(end - start);
    g_pooled[g * H1024 + f] = __float2half_rn(acc / fmaxf(cnt, 1.0f));
}

// ---------------- head: out[g,j] = head_b[j] + dot(z[g,:], head_w[:,j]) -----
__global__ __launch_bounds__(384) void k_head(const float* __restrict__ hw,
                                              const float* __restrict__ hb,
                                              float* __restrict__ out) {
    __shared__ float zs[FC];
    int g = blockIdx.x;
    for (int k = threadIdx.x; k < FC; k += blockDim.x)
        zs[k] = __half2float(g_z[(size_t)g * FC + k]);
    __syncthreads();
    int j = threadIdx.x;
    if (j >= NCLS) return;
    float acc = hb[j];
#pragma unroll 8
    for (int k = 0; k < FC; k++)
        acc = fmaf(zs[k], hw[(size_t)k * NCLS + j], acc);
    out[(size_t)g * NCLS + j] = acc;
}

// ---------------- host orchestration ---------------------------------------
static void fastgemm(int aId, int bOff, const float* bias, int cId,
                     int M, int N, int K, int relu) {
    dim3 grid(N / 256, (M + 127) / 128);
    k_fastgemm<<<grid, 256, FG_SMEM>>>(aId, bOff, bias, cId, M, N, K, relu);
}
static void wtT(const float* src, int off, int K, int Kpad, int N, cudaStream_t st) {
    dim3 grid(Kpad / 32, N / 32);
    k_wtT<<<grid, dim3(32, 8), 0, st>>>(src, off, K, Kpad, N);
}

extern "C" void kernel_launch(void* const* d_in, const int* in_sizes, int n_in,
                              void* d_out, int out_size) {
    const float* x         = (const float*)d_in[0];
    const float* edge_attr = (const float*)d_in[1];
    const void*  ei        = d_in[2];
    const void*  batch     = d_in[3];
    const float *emb_w1 = (const float*)d_in[4],  *emb_b1 = (const float*)d_in[5];
    const float *emb_w2 = (const float*)d_in[6],  *emb_b2 = (const float*)d_in[7];
    const float *ep_w1  = (const float*)d_in[8],  *ep_b1  = (const float*)d_in[9];
    const float *ep_w2  = (const float*)d_in[10], *ep_b2  = (const float*)d_in[11];
    const float *c6_w   = (const float*)d_in[12], *c6_b   = (const float*)d_in[13];
    const float *c7_w   = (const float*)d_in[14], *c7_b   = (const float*)d_in[15];
    const float *c8_w   = (const float*)d_in[16], *c8_b   = (const float*)d_in[17];
    const float *fc1_w  = (const float*)d_in[18], *fc1_b  = (const float*)d_in[19];
    const float *head_w = (const float*)d_in[20], *head_b = (const float*)d_in[21];
    float* out = (float*)d_out;

    static cudaStream_t sSide = nullptr;
    static cudaEvent_t evFork = nullptr, evJoin = nullptr;
    if (!sSide) {
        cudaStreamCreateWithFlags(&sSide, cudaStreamNonBlocking);
        cudaEventCreateWithFlags(&evFork, cudaEventDisableTiming);
        cudaEventCreateWithFlags(&evJoin, cudaEventDisableTiming);
        cudaFuncSetAttribute(k_fastgemm, cudaFuncAttributeMaxDynamicSharedMemorySize, FG_SMEM);
    }

    // ---- main stream: dtype detection (needed by both branches) ----
    k_detect<<<1, 256>>>((const unsigned int*)ei);

    // ---- fork: CSR build + conv/fc weight transposes on side stream ----
    cudaEventRecord(evFork, 0);
    cudaStreamWaitEvent(sSide, evFork, 0);

    k_init<<<NB_SCAN, 256, 0, sSide>>>();
    k_edge_mlp_deg<<<(EE + 255) / 256, 256, 0, sSide>>>(edge_attr, ep_w1, ep_b1, ep_w2, ep_b2, ei);
    k_scan_block<<<NB_SCAN, 256, 0, sSide>>>();   // also computes dis
    k_scan_tops<<<1, 256, 0, sSide>>>();
    k_scan_add<<<NB_SCAN, 256, 0, sSide>>>();
    k_fill<<<(EE + 255) / 256, 256, 0, sSide>>>(ei);
    wtT(c6_w, C6_OFF, H512, H512, H1024, sSide);
    wtT(c7_w, C7_OFF, H1024, H1024, H1024, sSide);
    wtT(c8_w, C8_OFF, H1024, H1024, H1024, sSide);
    wtT(fc1_w, FC1_OFF, H1024, H1024, FC, sSide);
    cudaEventRecord(evJoin, sSide);

    // ---- main stream: embedding path (independent of CSR) ----
    k_padx<<<(NN * 64 + 255) / 256, 256>>>(x);
    wtT(emb_w1, W1_OFF, FIN, 64, H512, 0);
    wtT(emb_w2, W2_OFF, H512, H512, H512, 0);
    fastgemm(BUF_A, W1_OFF, emb_b1, BUF_C, NN, H512, 64, 1);      // -> bufC
    fastgemm(BUF_C, W2_OFF, emb_b2, BUF_B, NN, H512, H512, 1);    // h -> bufB

    // ---- join: CSR + conv weights ready ----
    cudaStreamWaitEvent(0, evJoin, 0);

    // conv1: aggregate (512) then transform
    k_gather<<<NN, H512 / 8>>>(BUF_B, BUF_C, H512 / 8);           // agg(h) -> bufC
    fastgemm(BUF_C, C6_OFF, c6_b, BUF_A, NN, H1024, H512, 1);     // h1 -> bufA

    // conv2
    k_gather<<<NN, H1024 / 8>>>(BUF_A, BUF_C, H1024 / 8);
    fastgemm(BUF_C, C7_OFF, c7_b, BUF_B, NN, H1024, H1024, 1);    // h2 -> bufB

    // conv3
    k_gather<<<NN, H1024 / 8>>>(BUF_B, BUF_A, H1024 / 8);
    fastgemm(BUF_A, C8_OFF, c8_b, BUF_C, NN, H1024, H1024, 1);    // h3 -> bufC

    // mean pool
    dim3 pgrid(GG, H1024 / 256);
    k_pool2<<<pgrid, 256>>>(BUF_C, batch);

    // head
    fastgemm(BUF_POOLED, FC1_OFF, fc1_b, BUF_Z, GG, FC, H1024, 1); // z
    k_head<<<GG, 384>>>(head_w, head_b, out);
}